// round 9
// baseline (speedup 1.0000x reference)
#include <cuda_runtime.h>

#define FULLMASK 0xffffffffu
#define MINV 1e-12f
#define EPSV 1e-6f
#define MAXN (1.0f - 1e-5f)
#define KPI  (1.0f/0.66f)

#define NWARP 23
#define NTHR  (NWARP*32)

// shared layout (float offsets)
#define OFF_W4    0            // [2][64][128] packed lin_w
#define OFF_FW1T  16384        // [64][128]
#define OFF_FW2T  24576        // [128][128]
#define OFF_CONST 40960        // 912 floats
#define OFF_STAGE 41872
#define WSTRIDE   576
#define SOFF_WKM   512         // 32: wkm[mm*4+k], mm 0..7
#define SOFF_AARR  544         // 8
#define SOFF_MASK  552         // 8
#define SOFF_AXAGG 560         // 8
#define SOFF_XK    568         // 4
#define SMEM_FLOATS (OFF_STAGE + NWARP*WSTRIDE)
#define SMEM_BYTES  (SMEM_FLOATS*4)

__device__ float g_const[1024];
// 0 klp[4][64], 256 hb[4][64], 512 fb1h[128], 640 fb2h[128], 768 gb1h[64], 832 gb2h[64], 896 scal[12]

__device__ __forceinline__ float wred(float v){
    v += __shfl_xor_sync(FULLMASK, v, 16);
    v += __shfl_xor_sync(FULLMASK, v, 8);
    v += __shfl_xor_sync(FULLMASK, v, 4);
    v += __shfl_xor_sync(FULLMASK, v, 2);
    v += __shfl_xor_sync(FULLMASK, v, 1);
    return v;
}
__device__ __forceinline__ float tanh_pos(float xx){
    float e = __expf(-2.0f*xx);
    return __fdividef(1.0f - e, 1.0f + e);
}
__device__ __forceinline__ float artanh_c(float xx){
    xx = fminf(fmaxf(xx, -1.0f + EPSV), 1.0f - EPSV);
    return 0.5f*__logf(__fdividef(1.0f + xx, 1.0f - xx));
}
__device__ __forceinline__ float f4get(const float4 v, int i){
    return (i==0) ? v.x : (i==1) ? v.y : (i==2) ? v.z : v.w;
}

template<int V>
__device__ __forceinline__ void emap(const float* __restrict__ b, float* __restrict__ dst,
                                     float* __restrict__ n2dst, bool doproj){
    int l = threadIdx.x & 31;
    float u[V]; float s = 0.f;
    #pragma unroll
    for (int c=0;c<V;c++){ u[c] = b[V*l+c]; s += u[c]*u[c]; }
    float n2 = wred(s);
    float n  = sqrtf(fmaxf(n2, MINV));
    float f  = __fdividef(tanh_pos(n), n);
    float h2 = f*f*n2;
    if (doproj){
        float pn = sqrtf(fmaxf(h2, MINV));
        if (pn > MAXN){ f *= __fdividef(MAXN, pn); h2 = MAXN*MAXN; }
    }
    #pragma unroll
    for (int c=0;c<V;c++) dst[V*l+c] = f*u[c];
    if (l == 0) *n2dst = h2;
}

__global__ void prep_kernel(const float* __restrict__ kt, const float* __restrict__ lin_b,
                            const float* __restrict__ fb1, const float* __restrict__ fb2,
                            const float* __restrict__ gb1, const float* __restrict__ gb2){
    int w = threadIdx.x >> 5;
    if (w < 4){
        emap<2>(kt + w*64,    g_const + w*64,       g_const + 896 + w, false);
        emap<2>(lin_b + w*64, g_const + 256 + w*64, g_const + 900 + w, true);
    } else if (w == 4) emap<4>(fb1, g_const + 512, g_const + 904, true);
    else if (w == 5)   emap<4>(fb2, g_const + 640, g_const + 905, true);
    else if (w == 6)   emap<2>(gb1, g_const + 768, g_const + 906, true);
    else if (w == 7)   emap<2>(gb2, g_const + 832, g_const + 907, true);
}

template<int V>
__device__ __forceinline__ void blin_nl(float* h, const float* bvec, float b2,
                                        float ax_in, bool do_act,
                                        float& out_ax, float& out_n2){
    float s = 0.f;
    #pragma unroll
    for (int c=0;c<V;c++) s += h[c]*h[c];
    float mv2 = wred(s);
    float mvn = sqrtf(fmaxf(mv2, MINV));
    float fac = __fdividef(tanh_pos(mvn*ax_in), mvn);
    float f2  = fac*fac*mv2;
    { float pn = sqrtf(fmaxf(f2, MINV));
      if (pn > MAXN){ fac *= __fdividef(MAXN, pn); f2 = MAXN*MAXN; } }
    float mh = 0.f;
    #pragma unroll
    for (int c=0;c<V;c++) mh += h[c]*bvec[c];
    mh = wred(mh);
    float xy  = fac*mh;
    float A   = 1.0f + 2.0f*xy + b2;
    float B   = 1.0f - f2;
    float D   = fmaxf(1.0f + 2.0f*xy + f2*b2, MINV);
    float idn = __fdividef(1.0f, D);
    float r2  = (A*A*f2 + 2.0f*A*B*xy + B*B*b2)*idn*idn;
    float sp  = 1.0f;
    { float rn = sqrtf(fmaxf(r2, MINV));
      if (rn > MAXN){ sp = __fdividef(MAXN, rn); r2 = MAXN*MAXN; } }
    float cA = sp*idn*A*fac, cB = sp*idn*B;
    #pragma unroll
    for (int c=0;c<V;c++) h[c] = cA*h[c] + cB*bvec[c];
    if (do_act){
        float rn = sqrtf(fmaxf(r2, MINV));
        float lm = __fdividef(artanh_c(rn), rn);
        float t = 0.f;
        #pragma unroll
        for (int c=0;c<V;c++){ float u = fmaxf(h[c],0.f)*lm; h[c]=u; t += u*u; }
        float t2 = wred(t);
        float tn = sqrtf(fmaxf(t2, MINV));
        float ef = __fdividef(tanh_pos(tn), tn);
        float o2 = ef*ef*t2;
        float so = 1.0f;
        { float on = sqrtf(fmaxf(o2, MINV));
          if (on > MAXN){ so = __fdividef(MAXN, on); o2 = MAXN*MAXN; } }
        float cc = ef*so;
        #pragma unroll
        for (int c=0;c<V;c++) h[c] *= cc;
        r2 = o2;
    }
    out_n2 = r2;
    float nn = sqrtf(fmaxf(r2, MINV));
    out_ax = __fdividef(artanh_c(nn), nn);
}

__global__ void __launch_bounds__(NTHR, 1)
kp_main(const float* __restrict__ x, const int* __restrict__ nei,
        const float* __restrict__ neimask, const float* __restrict__ lin_w,
        const float* __restrict__ fw1, const float* __restrict__ fw2,
        const float* __restrict__ gw1, const float* __restrict__ gw2,
        float* __restrict__ out, int N)
{
    extern __shared__ float sm[];
    const int tid = threadIdx.x, wid = tid >> 5, l = tid & 31;

    for (int i = tid; i < 16384; i += NTHR){
        int p = i >> 13, r = i & 8191, row = r >> 7, q = r & 127;
        int lane = q >> 2, c = q & 3;
        int k = 2*p + (c >> 1), o = 2*lane + (c & 1);
        sm[OFF_W4 + i] = lin_w[k*4096 + o*64 + row];
    }
    for (int i = tid; i < 8192; i += NTHR){
        int o = i >> 6, ii = i & 63;
        sm[OFF_FW1T + ii*128 + o] = fw1[i];
    }
    for (int i = tid; i < 16384; i += NTHR){
        int o = i >> 7, ii = i & 127;
        sm[OFF_FW2T + ii*128 + o] = fw2[i];
    }
    for (int i = tid; i < 908; i += NTHR) sm[OFF_CONST + i] = g_const[i];
    __syncthreads();

    const int node = blockIdx.x*NWARP + wid;
    if (node >= N) return;

    float* S = sm + OFF_STAGE + wid*WSTRIDE;
    const float* KLP  = sm + OFF_CONST;
    const float* HB   = KLP + 256;
    const float* FB1H = KLP + 512;
    const float* FB2H = KLP + 640;
    const float* GB1H = KLP + 768;
    const float* GB2H = KLP + 832;
    const float* SC   = KLP + 896;

    // center point
    float2 xv = *(const float2*)(x + node*64 + 2*l);
    float x2 = wred(xv.x*xv.x + xv.y*xv.y);
    { float n = sqrtf(fmaxf(x2, MINV));
      if (n > MAXN){ float s = __fdividef(MAXN, n); xv.x*=s; xv.y*=s; x2 = MAXN*MAXN; } }

    // center-kernel dots (node-invariant) -> scratch
    {
        float xk[4];
        #pragma unroll
        for (int k=0;k<4;k++){
            float2 kp = *(const float2*)(KLP + k*64 + 2*l);
            xk[k] = wred(xv.x*kp.x + xv.y*kp.y);
        }
        if (l == 0) *(float4*)(S + SOFF_XK) = make_float4(xk[0], xk[1], xk[2], xk[3]);
    }
    __syncwarp();

    float mnum[4] = {0.f,0.f,0.f,0.f};
    float mden = 0.f;

    for (int g2 = 0; g2 < 2; g2++){           // 2 super-groups of 8 neighbors
        // ---- stage A: 2 sub-batches of 4 neighbors ----
        #pragma unroll 1
        for (int sb = 0; sb < 2; sb++){
            float d_n2 = 0.f, d_xdn = 0.f, d_nk = 0.f;
            #pragma unroll
            for (int mm=0; mm<4; mm++){
                const int m = g2*8 + sb*4 + mm;
                const int idx = __ldg(nei + node*16 + m);
                float2 v = *(const float2*)(x + idx*64 + 2*l);
                float n2 = wred(v.x*v.x + v.y*v.y);
                float nn = sqrtf(fmaxf(n2, MINV));
                if (nn > MAXN){ float s = __fdividef(MAXN, nn); v.x*=s; v.y*=s; n2 = MAXN*MAXN; }
                *(float2*)(S + (sb*4+mm)*64 + 2*l) = v;
                float xdn = wred(xv.x*v.x + xv.y*v.y);
                const bool quad = ((l>>2) == mm);
                if (quad){ d_n2 = n2; d_xdn = xdn; }
                #pragma unroll
                for (int k=0;k<4;k++){
                    float2 kp = *(const float2*)(KLP + k*64 + 2*l);
                    float nk = wred(v.x*kp.x + v.y*kp.y);
                    if (quad && (l&3)==k) d_nk = nk;
                }
            }
            {   // lane-parallel chain: lane j = mm*4+k
                const int mmj = (l >> 2) & 3, kj = l & 3;
                float xkj   = S[SOFF_XK + kj];
                float klp2j = SC[kj];
                float a   = 1.0f - 2.0f*d_xdn + d_n2;
                float b   = 1.0f - x2;
                float den = fmaxf(1.0f - 2.0f*d_xdn + x2*d_n2, MINV);
                float idn = __fdividef(1.0f, den);
                float x02 = (a*a*x2 - 2.0f*a*b*d_xdn + b*b*d_n2)*idn*idn;
                float s0  = 1.0f;
                { float n0 = sqrtf(fmaxf(x02, MINV));
                  if (n0 > MAXN){ s0 = __fdividef(MAXN, n0); x02 = MAXN*MAXN; } }
                float x0k = (-a*xkj + b*d_nk)*idn*s0;
                float A = 1.0f - 2.0f*x0k + klp2j;
                float B = 1.0f - x02;
                float D = fmaxf(1.0f - 2.0f*x0k + x02*klp2j, MINV);
                float iD = __fdividef(1.0f, D);
                float nsq = (A*A*x02 - 2.0f*A*B*x0k + B*B*klp2j)*iD*iD;
                float nd = sqrtf(fmaxf(nsq, MINV));
                float dd = 2.0f*artanh_c(nd);
                float wv = fmaxf(0.f, 1.0f - dd*KPI);
                float sw = wv + __shfl_xor_sync(FULLMASK, wv, 1);
                sw += __shfl_xor_sync(FULLMASK, sw, 2);
                float isw = __fdividef(1.0f, fmaxf(sw, MINV));
                if (l < 16){
                    S[SOFF_WKM + sb*16 + l] = wv*isw;
                    if (kj == 0){
                        float nn2 = sqrtf(fmaxf(d_n2, MINV));
                        S[SOFF_AARR + sb*4 + mmj] = __fdividef(artanh_c(nn2), nn2);
                        S[SOFF_MASK + sb*4 + mmj] = __ldg(neimask + node*16 + g2*8 + sb*4 + mmj);
                    }
                }
            }
            __syncwarp();
        }

        // ---- stage B: 8-wide, two k-pair passes ----
        float kn0[8], kn1[8];
        #pragma unroll
        for (int nb=0;nb<8;nb++){ kn0[nb]=0.f; kn1[nb]=0.f; }
        float kdnl = 0.f;                      // per-lane Klein-weight partial (lanes 0-15)
        #pragma unroll 1
        for (int p=0;p<2;p++){
            float acc[2][8][2];
            #pragma unroll
            for (int kk=0;kk<2;kk++)
                #pragma unroll
                for (int nb=0;nb<8;nb++){ acc[kk][nb][0]=0.f; acc[kk][nb][1]=0.f; }
            #pragma unroll 1
            for (int j4=0;j4<16;j4++){
                float4 xq[8];
                #pragma unroll
                for (int nb=0;nb<8;nb++) xq[nb] = *(const float4*)(S + nb*64 + j4*4);
                #pragma unroll
                for (int jj=0;jj<4;jj++){
                    float4 w4 = *(const float4*)(sm + OFF_W4 + p*8192 + (j4*4+jj)*128 + 4*l);
                    #pragma unroll
                    for (int nb=0;nb<8;nb++){
                        float xa = f4get(xq[nb], jj);
                        acc[0][nb][0] += w4.x*xa; acc[0][nb][1] += w4.y*xa;
                        acc[1][nb][0] += w4.z*xa; acc[1][nb][1] += w4.w*xa;
                    }
                }
            }
            // phase 1: reductions, deposit at lane j = kk*8+nb
            float2 hbv0 = *(const float2*)(HB + (2*p+0)*64 + 2*l);
            float2 hbv1 = *(const float2*)(HB + (2*p+1)*64 + 2*l);
            float d_mx2 = 0.f, d_mh = 0.f;
            #pragma unroll
            for (int kk=0;kk<2;kk++){
                float2 hbv = kk ? hbv1 : hbv0;
                #pragma unroll
                for (int nb=0;nb<8;nb++){
                    float a0=acc[kk][nb][0], a1=acc[kk][nb][1];
                    float mx2 = wred(a0*a0 + a1*a1);
                    float mh  = wred(a0*hbv.x + a1*hbv.y);
                    if (l == kk*8+nb){ d_mx2 = mx2; d_mh = mh; }
                }
            }
            // phase 2: lane-parallel chain (lanes 0-15 meaningful)
            float c1, c2;
            {
                const int kkj = (l >> 3) & 1, mmj = l & 7;
                const int kj = 2*p + kkj;
                float aa   = S[SOFF_AARR + mmj];
                float hb2k = SC[4 + kj];
                float wkmv = S[SOFF_WKM + mmj*4 + kj];
                float mxn = sqrtf(fmaxf(d_mx2, MINV));
                float fac = __fdividef(tanh_pos(mxn*aa), mxn);
                float f2  = fac*fac*d_mx2;
                { float pn = sqrtf(fmaxf(f2, MINV));
                  if (pn > MAXN){ fac *= __fdividef(MAXN, pn); f2 = MAXN*MAXN; } }
                float xy = fac*d_mh;
                float A = 1.0f + 2.0f*xy + hb2k;
                float B = 1.0f - f2;
                float D = fmaxf(1.0f + 2.0f*xy + f2*hb2k, MINV);
                float iD = __fdividef(1.0f, D);
                float r2 = (A*A*f2 + 2.0f*A*B*xy + B*B*hb2k)*iD*iD;
                float sp = 1.0f;
                { float rn = sqrtf(fmaxf(r2, MINV));
                  if (rn > MAXN){ sp = __fdividef(MAXN, rn); r2 = MAXN*MAXN; } }
                float fk  = __fdividef(2.0f, 1.0f + r2);
                float kk2 = fk*fk*r2;
                float lor = rsqrtf(fmaxf(1.0f - kk2, MINV));
                float cwv = wkmv*lor;
                float cf  = cwv*fk*sp*iD;
                c1 = cf*A*fac;
                c2 = cf*B;
                if (l < 16) kdnl += cwv;
            }
            // phase 3: broadcast coefficients, accumulate Klein vectors
            #pragma unroll
            for (int kk=0;kk<2;kk++){
                float2 hbv = kk ? hbv1 : hbv0;
                #pragma unroll
                for (int nb=0;nb<8;nb++){
                    const int j = kk*8+nb;
                    float c1j = __shfl_sync(FULLMASK, c1, j);
                    float c2j = __shfl_sync(FULLMASK, c2, j);
                    kn0[nb] += c1j*acc[kk][nb][0] + c2j*hbv.x;
                    kn1[nb] += c1j*acc[kk][nb][1] + c2j*hbv.y;
                }
            }
        }
        __syncwarp();

        // ---- stage C: Klein midpoint normalize -> agg (rows 0-3 staged, 4-7 in regs) ----
        float kq = kdnl + __shfl_xor_sync(FULLMASK, kdnl, 8);   // lanes 0-7: kdn[nb]
        float agg47[4][2];
        #pragma unroll
        for (int nb=0;nb<8;nb++){
            float kd = __shfl_sync(FULLMASK, kq, nb);
            float ikd = __fdividef(1.0f, fmaxf(kd, MINV));
            float k0 = kn0[nb]*ikd, k1 = kn1[nb]*ikd;
            float kk2 = wred(k0*k0 + k1*k1);
            float s2 = __fdividef(1.0f, 1.0f + sqrtf(fmaxf(1.0f - kk2, MINV)));
            float p0 = s2*k0, p1 = s2*k1;
            float p2 = s2*s2*kk2;
            float spp = 1.0f;
            { float pn = sqrtf(fmaxf(p2, MINV));
              if (pn > MAXN){ spp = __fdividef(MAXN, pn); p2 = MAXN*MAXN; } }
            p0 *= spp; p1 *= spp;
            if (l == 0){
                float nn = sqrtf(fmaxf(p2, MINV));
                S[SOFF_AXAGG + nb] = __fdividef(artanh_c(nn), nn);
            }
            if (nb < 4) *(float2*)(S + nb*64 + 2*l) = make_float2(p0, p1);
            else { agg47[nb-4][0] = p0; agg47[nb-4][1] = p1; }
        }
        __syncwarp();

        // ---- stages D1/D2 in two 4-row halves ----
        #pragma unroll 1
        for (int half = 0; half < 2; half++){
            if (half == 1){
                #pragma unroll
                for (int mm=0;mm<4;mm++)
                    *(float2*)(S + mm*64 + 2*l) = make_float2(agg47[mm][0], agg47[mm][1]);
                __syncwarp();
            }
            // D1
            float h1[4][4];
            #pragma unroll
            for (int mm=0;mm<4;mm++)
                #pragma unroll
                for (int c=0;c<4;c++) h1[mm][c] = 0.f;
            #pragma unroll 2
            for (int j4=0;j4<16;j4++){
                float4 xq0 = *(const float4*)(S + 0*64 + j4*4);
                float4 xq1 = *(const float4*)(S + 1*64 + j4*4);
                float4 xq2 = *(const float4*)(S + 2*64 + j4*4);
                float4 xq3 = *(const float4*)(S + 3*64 + j4*4);
                #pragma unroll
                for (int jj=0;jj<4;jj++){
                    float4 wv = *(const float4*)(sm + OFF_FW1T + (j4*4+jj)*128 + 4*l);
                    float xa0=f4get(xq0,jj), xa1=f4get(xq1,jj), xa2=f4get(xq2,jj), xa3=f4get(xq3,jj);
                    h1[0][0]+=wv.x*xa0; h1[0][1]+=wv.y*xa0; h1[0][2]+=wv.z*xa0; h1[0][3]+=wv.w*xa0;
                    h1[1][0]+=wv.x*xa1; h1[1][1]+=wv.y*xa1; h1[1][2]+=wv.z*xa1; h1[1][3]+=wv.w*xa1;
                    h1[2][0]+=wv.x*xa2; h1[2][1]+=wv.y*xa2; h1[2][2]+=wv.z*xa2; h1[2][3]+=wv.w*xa2;
                    h1[3][0]+=wv.x*xa3; h1[3][1]+=wv.y*xa3; h1[3][2]+=wv.z*xa3; h1[3][3]+=wv.w*xa3;
                }
            }
            __syncwarp();
            float ax1[4];
            {
                float bv1[4] = {FB1H[4*l], FB1H[4*l+1], FB1H[4*l+2], FB1H[4*l+3]};
                const float fb1h2 = SC[8];
                #pragma unroll
                for (int mm=0;mm<4;mm++){
                    float n2o;
                    blin_nl<4>(h1[mm], bv1, fb1h2, S[SOFF_AXAGG + half*4 + mm], true, ax1[mm], n2o);
                    *(float4*)(S + mm*128 + 4*l) = make_float4(h1[mm][0], h1[mm][1], h1[mm][2], h1[mm][3]);
                }
            }
            __syncwarp();
            // D2
            float h2a[4][4];
            #pragma unroll
            for (int mm=0;mm<4;mm++)
                #pragma unroll
                for (int c=0;c<4;c++) h2a[mm][c] = 0.f;
            #pragma unroll 2
            for (int j4=0;j4<32;j4++){
                float4 xq0 = *(const float4*)(S + 0*128 + j4*4);
                float4 xq1 = *(const float4*)(S + 1*128 + j4*4);
                float4 xq2 = *(const float4*)(S + 2*128 + j4*4);
                float4 xq3 = *(const float4*)(S + 3*128 + j4*4);
                #pragma unroll
                for (int jj=0;jj<4;jj++){
                    float4 wv = *(const float4*)(sm + OFF_FW2T + (j4*4+jj)*128 + 4*l);
                    float xa0=f4get(xq0,jj), xa1=f4get(xq1,jj), xa2=f4get(xq2,jj), xa3=f4get(xq3,jj);
                    h2a[0][0]+=wv.x*xa0; h2a[0][1]+=wv.y*xa0; h2a[0][2]+=wv.z*xa0; h2a[0][3]+=wv.w*xa0;
                    h2a[1][0]+=wv.x*xa1; h2a[1][1]+=wv.y*xa1; h2a[1][2]+=wv.z*xa1; h2a[1][3]+=wv.w*xa1;
                    h2a[2][0]+=wv.x*xa2; h2a[2][1]+=wv.y*xa2; h2a[2][2]+=wv.z*xa2; h2a[2][3]+=wv.w*xa2;
                    h2a[3][0]+=wv.x*xa3; h2a[3][1]+=wv.y*xa3; h2a[3][2]+=wv.z*xa3; h2a[3][3]+=wv.w*xa3;
                }
            }
            {
                float bv2[4] = {FB2H[4*l], FB2H[4*l+1], FB2H[4*l+2], FB2H[4*l+3]};
                const float fb2h2 = SC[9];
                #pragma unroll
                for (int mm=0;mm<4;mm++){
                    float axo, r2o;
                    blin_nl<4>(h2a[mm], bv2, fb2h2, ax1[mm], false, axo, r2o);
                    float fk  = __fdividef(2.0f, 1.0f + r2o);
                    float kk2 = fk*fk*r2o;
                    float lor = rsqrtf(fmaxf(1.0f - kk2, MINV));
                    float cw  = S[SOFF_MASK + half*4 + mm]*lor;
                    float cf  = cw*fk;
                    mden += cw;
                    #pragma unroll
                    for (int c=0;c<4;c++) mnum[c] += cf*h2a[mm][c];
                }
            }
            __syncwarp();
        }
    }

    // ---- neighbor Klein midpoint -> mid (128-d) ----
    float imd = __fdividef(1.0f, fmaxf(mden, MINV));
    float mk4[4]; float s = 0.f;
    #pragma unroll
    for (int c=0;c<4;c++){ mk4[c] = mnum[c]*imd; s += mk4[c]*mk4[c]; }
    float kk2 = wred(s);
    float s2 = __fdividef(1.0f, 1.0f + sqrtf(fmaxf(1.0f - kk2, MINV)));
    float p2 = s2*s2*kk2;
    float spp = 1.0f;
    { float pn = sqrtf(fmaxf(p2, MINV));
      if (pn > MAXN){ spp = __fdividef(MAXN, pn); p2 = MAXN*MAXN; } }
    float cc = s2*spp;
    #pragma unroll
    for (int c=0;c<4;c++) mk4[c] *= cc;
    *(float4*)(S + 4*l) = make_float4(mk4[0], mk4[1], mk4[2], mk4[3]);
    float axmid;
    { float nn = sqrtf(fmaxf(p2, MINV)); axmid = __fdividef(artanh_c(nn), nn); }
    __syncwarp();

    // ---- tail E1: out1 = blinear(mid, gw1, gb1, relu) ----
    float g1v[2] = {0.f, 0.f};
    #pragma unroll 4
    for (int i4=0;i4<32;i4++){
        float4 xs = *(const float4*)(S + i4*4);
        float4 w0 = __ldg((const float4*)(gw1 + (2*l)*128 + i4*4));
        float4 w1 = __ldg((const float4*)(gw1 + (2*l+1)*128 + i4*4));
        g1v[0] += w0.x*xs.x + w0.y*xs.y + w0.z*xs.z + w0.w*xs.w;
        g1v[1] += w1.x*xs.x + w1.y*xs.y + w1.z*xs.z + w1.w*xs.w;
    }
    __syncwarp();
    float axo1, r2o1;
    {
        float bvg1[2] = {GB1H[2*l], GB1H[2*l+1]};
        blin_nl<2>(g1v, bvg1, SC[10], axmid, true, axo1, r2o1);
    }
    *(float2*)(S + 2*l) = make_float2(g1v[0], g1v[1]);
    __syncwarp();

    // ---- tail E2: out = blinear(out1, gw2, gb2) ----
    float g2v[2] = {0.f, 0.f};
    #pragma unroll 4
    for (int i4=0;i4<16;i4++){
        float4 xs = *(const float4*)(S + i4*4);
        float4 w0 = __ldg((const float4*)(gw2 + (2*l)*64 + i4*4));
        float4 w1 = __ldg((const float4*)(gw2 + (2*l+1)*64 + i4*4));
        g2v[0] += w0.x*xs.x + w0.y*xs.y + w0.z*xs.z + w0.w*xs.w;
        g2v[1] += w1.x*xs.x + w1.y*xs.y + w1.z*xs.z + w1.w*xs.w;
    }
    float axo2, r2o2;
    {
        float bvg2[2] = {GB2H[2*l], GB2H[2*l+1]};
        blin_nl<2>(g2v, bvg2, SC[11], axo1, false, axo2, r2o2);
    }
    *(float2*)(out + node*64 + 2*l) = make_float2(g2v[0], g2v[1]);
}

extern "C" void kernel_launch(void* const* d_in, const int* in_sizes, int n_in,
                              void* d_out, int out_size){
    const float* x       = (const float*)d_in[0];
    const int*   nei     = (const int*)  d_in[1];
    const float* neimask = (const float*)d_in[2];
    const float* kt      = (const float*)d_in[3];
    const float* lin_w   = (const float*)d_in[4];
    const float* lin_b   = (const float*)d_in[5];
    const float* fw1     = (const float*)d_in[6];
    const float* fb1     = (const float*)d_in[7];
    const float* fw2     = (const float*)d_in[8];
    const float* fb2     = (const float*)d_in[9];
    const float* gw1     = (const float*)d_in[10];
    const float* gb1     = (const float*)d_in[11];
    const float* gw2     = (const float*)d_in[12];
    const float* gb2     = (const float*)d_in[13];
    float* out = (float*)d_out;
    const int N = in_sizes[0]/64;

    cudaFuncSetAttribute(kp_main, cudaFuncAttributeMaxDynamicSharedMemorySize, SMEM_BYTES);
    prep_kernel<<<1, 256>>>(kt, lin_b, fb1, fb2, gb1, gb2);
    kp_main<<<(N + NWARP - 1)/NWARP, NTHR, SMEM_BYTES>>>(x, nei, neimask, lin_w, fw1, fw2, gw1, gw2, out, N);
}

// round 10
// speedup vs baseline: 1.0644x; 1.0644x over previous
#include <cuda_runtime.h>
#include <cuda_fp16.h>

#define FULLMASK 0xffffffffu
#define MINV 1e-12f
#define EPSV 1e-6f
#define MAXN (1.0f - 1e-5f)
#define KPI  (1.0f/0.66f)

#define NWARP 28
#define NTHR  (NWARP*32)

// shared layout (float offsets)
#define OFF_W4H   0            // fp16 packed lin_w: [2][32 rowpairs][256 halves] = 8192 floats
#define OFF_FW1H  8192         // fp16 fw1T: [32 rowpairs][256 halves] = 4096 floats
#define OFF_FW2H  12288        // fp16 fw2T: [64 rowpairs][256 halves] = 8192 floats
#define OFF_CONST 20480        // 912 floats
#define OFF_STAGE 21392
#define WSTRIDE   544
#define SOFF_WKM  512          // 16: wkm[mm*4+k]
#define SOFF_AARR 528          // 4
#define SOFF_MASK 532          // 4
#define SOFF_XK   536          // 4
#define SMEM_FLOATS (OFF_STAGE + NWARP*WSTRIDE)
#define SMEM_BYTES  (SMEM_FLOATS*4)

__device__ float g_const[1024];
// 0 klp[4][64], 256 hb[4][64], 512 fb1h[128], 640 fb2h[128], 768 gb1h[64], 832 gb2h[64], 896 scal[12]

__device__ __forceinline__ float wred(float v){
    v += __shfl_xor_sync(FULLMASK, v, 16);
    v += __shfl_xor_sync(FULLMASK, v, 8);
    v += __shfl_xor_sync(FULLMASK, v, 4);
    v += __shfl_xor_sync(FULLMASK, v, 2);
    v += __shfl_xor_sync(FULLMASK, v, 1);
    return v;
}
__device__ __forceinline__ float tanh_pos(float xx){
    float e = __expf(-2.0f*xx);
    return __fdividef(1.0f - e, 1.0f + e);
}
__device__ __forceinline__ float artanh_c(float xx){
    xx = fminf(fmaxf(xx, -1.0f + EPSV), 1.0f - EPSV);
    return 0.5f*__logf(__fdividef(1.0f + xx, 1.0f - xx));
}
__device__ __forceinline__ float f4get(const float4 v, int i){
    return (i==0) ? v.x : (i==1) ? v.y : (i==2) ? v.z : v.w;
}
// unpack two packed half2 words into a float4 weight quad
__device__ __forceinline__ float4 cvt_w4(unsigned u01, unsigned u23){
    float2 f01 = __half22float2(*(const __half2*)&u01);
    float2 f23 = __half22float2(*(const __half2*)&u23);
    return make_float4(f01.x, f01.y, f23.x, f23.y);
}

template<int V>
__device__ __forceinline__ void emap(const float* __restrict__ b, float* __restrict__ dst,
                                     float* __restrict__ n2dst, bool doproj){
    int l = threadIdx.x & 31;
    float u[V]; float s = 0.f;
    #pragma unroll
    for (int c=0;c<V;c++){ u[c] = b[V*l+c]; s += u[c]*u[c]; }
    float n2 = wred(s);
    float n  = sqrtf(fmaxf(n2, MINV));
    float f  = __fdividef(tanh_pos(n), n);
    float h2 = f*f*n2;
    if (doproj){
        float pn = sqrtf(fmaxf(h2, MINV));
        if (pn > MAXN){ f *= __fdividef(MAXN, pn); h2 = MAXN*MAXN; }
    }
    #pragma unroll
    for (int c=0;c<V;c++) dst[V*l+c] = f*u[c];
    if (l == 0) *n2dst = h2;
}

__global__ void prep_kernel(const float* __restrict__ kt, const float* __restrict__ lin_b,
                            const float* __restrict__ fb1, const float* __restrict__ fb2,
                            const float* __restrict__ gb1, const float* __restrict__ gb2){
    int w = threadIdx.x >> 5;
    if (w < 4){
        emap<2>(kt + w*64,    g_const + w*64,       g_const + 896 + w, false);
        emap<2>(lin_b + w*64, g_const + 256 + w*64, g_const + 900 + w, true);
    } else if (w == 4) emap<4>(fb1, g_const + 512, g_const + 904, true);
    else if (w == 5)   emap<4>(fb2, g_const + 640, g_const + 905, true);
    else if (w == 6)   emap<2>(gb1, g_const + 768, g_const + 906, true);
    else if (w == 7)   emap<2>(gb2, g_const + 832, g_const + 907, true);
}

template<int V>
__device__ __forceinline__ void blin_nl(float* h, const float* bvec, float b2,
                                        float ax_in, bool do_act,
                                        float& out_ax, float& out_n2){
    float s = 0.f;
    #pragma unroll
    for (int c=0;c<V;c++) s += h[c]*h[c];
    float mv2 = wred(s);
    float mvn = sqrtf(fmaxf(mv2, MINV));
    float fac = __fdividef(tanh_pos(mvn*ax_in), mvn);
    float f2  = fac*fac*mv2;
    { float pn = sqrtf(fmaxf(f2, MINV));
      if (pn > MAXN){ fac *= __fdividef(MAXN, pn); f2 = MAXN*MAXN; } }
    float mh = 0.f;
    #pragma unroll
    for (int c=0;c<V;c++) mh += h[c]*bvec[c];
    mh = wred(mh);
    float xy  = fac*mh;
    float A   = 1.0f + 2.0f*xy + b2;
    float B   = 1.0f - f2;
    float D   = fmaxf(1.0f + 2.0f*xy + f2*b2, MINV);
    float idn = __fdividef(1.0f, D);
    float r2  = (A*A*f2 + 2.0f*A*B*xy + B*B*b2)*idn*idn;
    float sp  = 1.0f;
    { float rn = sqrtf(fmaxf(r2, MINV));
      if (rn > MAXN){ sp = __fdividef(MAXN, rn); r2 = MAXN*MAXN; } }
    float cA = sp*idn*A*fac, cB = sp*idn*B;
    #pragma unroll
    for (int c=0;c<V;c++) h[c] = cA*h[c] + cB*bvec[c];
    if (do_act){
        float rn = sqrtf(fmaxf(r2, MINV));
        float lm = __fdividef(artanh_c(rn), rn);
        float t = 0.f;
        #pragma unroll
        for (int c=0;c<V;c++){ float u = fmaxf(h[c],0.f)*lm; h[c]=u; t += u*u; }
        float t2 = wred(t);
        float tn = sqrtf(fmaxf(t2, MINV));
        float ef = __fdividef(tanh_pos(tn), tn);
        float o2 = ef*ef*t2;
        float so = 1.0f;
        { float on = sqrtf(fmaxf(o2, MINV));
          if (on > MAXN){ so = __fdividef(MAXN, on); o2 = MAXN*MAXN; } }
        float cc = ef*so;
        #pragma unroll
        for (int c=0;c<V;c++) h[c] *= cc;
        r2 = o2;
    }
    out_n2 = r2;
    float nn = sqrtf(fmaxf(r2, MINV));
    out_ax = __fdividef(artanh_c(nn), nn);
}

__global__ void __launch_bounds__(NTHR, 1)
kp_main(const float* __restrict__ x, const int* __restrict__ nei,
        const float* __restrict__ neimask, const float* __restrict__ lin_w,
        const float* __restrict__ fw1, const float* __restrict__ fw2,
        const float* __restrict__ gw1, const float* __restrict__ gw2,
        float* __restrict__ out, int N)
{
    extern __shared__ float sm[];
    const int tid = threadIdx.x, wid = tid >> 5, l = tid & 31;

    __half* HW  = (__half*)(sm + OFF_W4H);
    __half* HF1 = (__half*)(sm + OFF_FW1H);
    __half* HF2 = (__half*)(sm + OFF_FW2H);

    // lin_w -> fp16 packed: half idx = p*8192 + j2*256 + lane*8 + r01*4 + kk*2 + oo
    for (int i = tid; i < 16384; i += NTHR){
        int p = i >> 13, rem = i & 8191, j2 = rem >> 8, q = rem & 255;
        int lane = q >> 3, c8 = q & 7, r01 = c8 >> 2, kk = (c8 >> 1) & 1, oo = c8 & 1;
        int row = 2*j2 + r01, k = 2*p + kk, o = 2*lane + oo;
        HW[i] = __float2half_rn(lin_w[k*4096 + o*64 + row]);
    }
    // fw1 -> fp16 packed: half idx = j2*256 + lane*8 + r01*4 + c ; o = 4*lane+c, row = 2*j2+r01
    for (int i = tid; i < 8192; i += NTHR){
        int j2 = i >> 8, q = i & 255, lane = q >> 3, c8 = q & 7, r01 = c8 >> 2, c = c8 & 3;
        int row = 2*j2 + r01, o = 4*lane + c;
        HF1[i] = __float2half_rn(fw1[o*64 + row]);
    }
    // fw2 -> fp16 packed (same scheme, 128 rows)
    for (int i = tid; i < 16384; i += NTHR){
        int j2 = i >> 8, q = i & 255, lane = q >> 3, c8 = q & 7, r01 = c8 >> 2, c = c8 & 3;
        int row = 2*j2 + r01, o = 4*lane + c;
        HF2[i] = __float2half_rn(fw2[o*128 + row]);
    }
    for (int i = tid; i < 908; i += NTHR) sm[OFF_CONST + i] = g_const[i];
    __syncthreads();

    const int node = blockIdx.x*NWARP + wid;
    if (node >= N) return;

    float* S = sm + OFF_STAGE + wid*WSTRIDE;
    const float* KLP  = sm + OFF_CONST;
    const float* HB   = KLP + 256;
    const float* FB1H = KLP + 512;
    const float* FB2H = KLP + 640;
    const float* GB1H = KLP + 768;
    const float* GB2H = KLP + 832;
    const float* SC   = KLP + 896;

    // center point
    float2 xv = *(const float2*)(x + node*64 + 2*l);
    float x2 = wred(xv.x*xv.x + xv.y*xv.y);
    { float n = sqrtf(fmaxf(x2, MINV));
      if (n > MAXN){ float s = __fdividef(MAXN, n); xv.x*=s; xv.y*=s; x2 = MAXN*MAXN; } }

    // center-kernel dots (node-invariant) -> scratch
    {
        float xk[4];
        #pragma unroll
        for (int k=0;k<4;k++){
            float2 kp = *(const float2*)(KLP + k*64 + 2*l);
            xk[k] = wred(xv.x*kp.x + xv.y*kp.y);
        }
        if (l == 0) *(float4*)(S + SOFF_XK) = make_float4(xk[0], xk[1], xk[2], xk[3]);
    }
    __syncwarp();

    float mnum[4] = {0.f,0.f,0.f,0.f};
    float mden = 0.f;

    for (int g = 0; g < 4; g++){
        // ---- stage A phase 1: gather/proj + warp reductions, deposit into lanes ----
        float d_n2 = 0.f, d_xdn = 0.f, d_nk = 0.f;
        #pragma unroll
        for (int mm=0; mm<4; mm++){
            const int m = g*4 + mm;
            const int idx = __ldg(nei + node*16 + m);
            float2 v = *(const float2*)(x + idx*64 + 2*l);
            float n2 = wred(v.x*v.x + v.y*v.y);
            float nn = sqrtf(fmaxf(n2, MINV));
            if (nn > MAXN){ float s = __fdividef(MAXN, nn); v.x*=s; v.y*=s; n2 = MAXN*MAXN; }
            *(float2*)(S + mm*64 + 2*l) = v;
            float xdn = wred(xv.x*v.x + xv.y*v.y);
            const bool quad = ((l>>2) == mm);
            if (quad){ d_n2 = n2; d_xdn = xdn; }
            #pragma unroll
            for (int k=0;k<4;k++){
                float2 kp = *(const float2*)(KLP + k*64 + 2*l);
                float nk = wred(v.x*kp.x + v.y*kp.y);
                if (quad && (l&3)==k) d_nk = nk;
            }
        }
        // ---- stage A phase 2: one lane-parallel chain; lane j=mm*4+k handles (mm,k) ----
        {
            const int mmj = (l >> 2) & 3, kj = l & 3;
            float xkj   = S[SOFF_XK + kj];
            float klp2j = SC[kj];
            float a   = 1.0f - 2.0f*d_xdn + d_n2;
            float b   = 1.0f - x2;
            float den = fmaxf(1.0f - 2.0f*d_xdn + x2*d_n2, MINV);
            float idn = __fdividef(1.0f, den);
            float x02 = (a*a*x2 - 2.0f*a*b*d_xdn + b*b*d_n2)*idn*idn;
            float s0  = 1.0f;
            { float n0 = sqrtf(fmaxf(x02, MINV));
              if (n0 > MAXN){ s0 = __fdividef(MAXN, n0); x02 = MAXN*MAXN; } }
            float x0k = (-a*xkj + b*d_nk)*idn*s0;
            float A = 1.0f - 2.0f*x0k + klp2j;
            float B = 1.0f - x02;
            float D = fmaxf(1.0f - 2.0f*x0k + x02*klp2j, MINV);
            float iD = __fdividef(1.0f, D);
            float nsq = (A*A*x02 - 2.0f*A*B*x0k + B*B*klp2j)*iD*iD;
            float nd = sqrtf(fmaxf(nsq, MINV));
            float dd = 2.0f*artanh_c(nd);
            float wv = fmaxf(0.f, 1.0f - dd*KPI);
            float sw = wv + __shfl_xor_sync(FULLMASK, wv, 1);
            sw += __shfl_xor_sync(FULLMASK, sw, 2);
            float isw = __fdividef(1.0f, fmaxf(sw, MINV));
            if (l < 16){
                S[SOFF_WKM + l] = wv*isw;
                if (kj == 0){
                    float nn2 = sqrtf(fmaxf(d_n2, MINV));
                    S[SOFF_AARR + mmj] = __fdividef(artanh_c(nn2), nn2);
                    S[SOFF_MASK + mmj] = __ldg(neimask + node*16 + g*4 + mmj);
                }
            }
        }
        __syncwarp();

        // ---- stage B: two k-pair passes; fp16 weights; lane-parallel epilogue ----
        float kn0[4], kn1[4], kdn[4];
        #pragma unroll
        for (int mm=0;mm<4;mm++){ kn0[mm]=0.f; kn1[mm]=0.f; kdn[mm]=0.f; }
        #pragma unroll 1
        for (int p=0;p<2;p++){
            float acc[2][4][2];
            #pragma unroll
            for (int kk=0;kk<2;kk++)
                #pragma unroll
                for (int mm=0;mm<4;mm++){ acc[kk][mm][0]=0.f; acc[kk][mm][1]=0.f; }
            #pragma unroll 2
            for (int j4=0;j4<16;j4++){
                float4 xq0 = *(const float4*)(S + 0*64 + j4*4);
                float4 xq1 = *(const float4*)(S + 1*64 + j4*4);
                float4 xq2 = *(const float4*)(S + 2*64 + j4*4);
                float4 xq3 = *(const float4*)(S + 3*64 + j4*4);
                uint4 wa = *(const uint4*)(HW + p*8192 + (2*j4+0)*256 + 8*l);
                uint4 wb = *(const uint4*)(HW + p*8192 + (2*j4+1)*256 + 8*l);
                #pragma unroll
                for (int jj=0;jj<4;jj++){
                    unsigned u01 = (jj==0)?wa.x:(jj==1)?wa.z:(jj==2)?wb.x:wb.z;
                    unsigned u23 = (jj==0)?wa.y:(jj==1)?wa.w:(jj==2)?wb.y:wb.w;
                    float4 w4 = cvt_w4(u01, u23);
                    float xa0=f4get(xq0,jj), xa1=f4get(xq1,jj), xa2=f4get(xq2,jj), xa3=f4get(xq3,jj);
                    acc[0][0][0] += w4.x*xa0; acc[0][0][1] += w4.y*xa0;
                    acc[1][0][0] += w4.z*xa0; acc[1][0][1] += w4.w*xa0;
                    acc[0][1][0] += w4.x*xa1; acc[0][1][1] += w4.y*xa1;
                    acc[1][1][0] += w4.z*xa1; acc[1][1][1] += w4.w*xa1;
                    acc[0][2][0] += w4.x*xa2; acc[0][2][1] += w4.y*xa2;
                    acc[1][2][0] += w4.z*xa2; acc[1][2][1] += w4.w*xa2;
                    acc[0][3][0] += w4.x*xa3; acc[0][3][1] += w4.y*xa3;
                    acc[1][3][0] += w4.z*xa3; acc[1][3][1] += w4.w*xa3;
                }
            }
            // epilogue phase 1: reductions + lane deposits (lane j = kk*4+mm)
            float2 hbv0 = *(const float2*)(HB + (2*p+0)*64 + 2*l);
            float2 hbv1 = *(const float2*)(HB + (2*p+1)*64 + 2*l);
            float d_mx2 = 0.f, d_mh = 0.f;
            #pragma unroll
            for (int kk=0;kk<2;kk++){
                float2 hbv = kk ? hbv1 : hbv0;
                #pragma unroll
                for (int mm=0;mm<4;mm++){
                    float a0=acc[kk][mm][0], a1=acc[kk][mm][1];
                    float mx2 = wred(a0*a0 + a1*a1);
                    float mh  = wred(a0*hbv.x + a1*hbv.y);
                    if (l == kk*4+mm){ d_mx2 = mx2; d_mh = mh; }
                }
            }
            // epilogue phase 2: one lane-parallel chain (lanes 0-7 meaningful)
            float c1, c2, cwv;
            {
                const int kkj = (l >> 2) & 1, mmj = l & 3;
                const int kj = 2*p + kkj;
                float aa   = S[SOFF_AARR + mmj];
                float hb2k = SC[4 + kj];
                float wkmv = S[SOFF_WKM + mmj*4 + kj];
                float mxn = sqrtf(fmaxf(d_mx2, MINV));
                float fac = __fdividef(tanh_pos(mxn*aa), mxn);
                float f2  = fac*fac*d_mx2;
                { float pn = sqrtf(fmaxf(f2, MINV));
                  if (pn > MAXN){ fac *= __fdividef(MAXN, pn); f2 = MAXN*MAXN; } }
                float xy = fac*d_mh;
                float A = 1.0f + 2.0f*xy + hb2k;
                float B = 1.0f - f2;
                float D = fmaxf(1.0f + 2.0f*xy + f2*hb2k, MINV);
                float iD = __fdividef(1.0f, D);
                float r2 = (A*A*f2 + 2.0f*A*B*xy + B*B*hb2k)*iD*iD;
                float sp = 1.0f;
                { float rn = sqrtf(fmaxf(r2, MINV));
                  if (rn > MAXN){ sp = __fdividef(MAXN, rn); r2 = MAXN*MAXN; } }
                float fk  = __fdividef(2.0f, 1.0f + r2);
                float kk2 = fk*fk*r2;
                float lor = rsqrtf(fmaxf(1.0f - kk2, MINV));
                cwv = wkmv*lor;
                float cf  = cwv*fk*sp*iD;
                c1 = cf*A*fac;
                c2 = cf*B;
            }
            // epilogue phase 3: broadcast coefficients, accumulate Klein sums
            #pragma unroll
            for (int kk=0;kk<2;kk++){
                float2 hbv = kk ? hbv1 : hbv0;
                #pragma unroll
                for (int mm=0;mm<4;mm++){
                    const int j = kk*4+mm;
                    float c1j = __shfl_sync(FULLMASK, c1, j);
                    float c2j = __shfl_sync(FULLMASK, c2, j);
                    float cwj = __shfl_sync(FULLMASK, cwv, j);
                    kn0[mm] += c1j*acc[kk][mm][0] + c2j*hbv.x;
                    kn1[mm] += c1j*acc[kk][mm][1] + c2j*hbv.y;
                    kdn[mm] += cwj;
                }
            }
        }
        __syncwarp();

        // ---- stage C: Klein midpoint normalize -> agg ----
        float axagg[4];
        #pragma unroll
        for (int mm=0;mm<4;mm++){
            float ikd = __fdividef(1.0f, fmaxf(kdn[mm], MINV));
            float k0 = kn0[mm]*ikd, k1 = kn1[mm]*ikd;
            float kk2 = wred(k0*k0 + k1*k1);
            float s2 = __fdividef(1.0f, 1.0f + sqrtf(fmaxf(1.0f - kk2, MINV)));
            float p0 = s2*k0, p1 = s2*k1;
            float p2 = s2*s2*kk2;
            float spp = 1.0f;
            { float pn = sqrtf(fmaxf(p2, MINV));
              if (pn > MAXN){ spp = __fdividef(MAXN, pn); p2 = MAXN*MAXN; } }
            p0 *= spp; p1 *= spp;
            { float nn = sqrtf(fmaxf(p2, MINV)); axagg[mm] = __fdividef(artanh_c(nn), nn); }
            *(float2*)(S + mm*64 + 2*l) = make_float2(p0, p1);
        }
        __syncwarp();

        // ---- stage D1: h1 = blinear(agg, fw1, fb1, relu), fp16 weights ----
        float h1[4][4];
        #pragma unroll
        for (int mm=0;mm<4;mm++)
            #pragma unroll
            for (int c=0;c<4;c++) h1[mm][c] = 0.f;
        #pragma unroll 2
        for (int j4=0;j4<16;j4++){
            float4 xq0 = *(const float4*)(S + 0*64 + j4*4);
            float4 xq1 = *(const float4*)(S + 1*64 + j4*4);
            float4 xq2 = *(const float4*)(S + 2*64 + j4*4);
            float4 xq3 = *(const float4*)(S + 3*64 + j4*4);
            uint4 wa = *(const uint4*)(HF1 + (2*j4+0)*256 + 8*l);
            uint4 wb = *(const uint4*)(HF1 + (2*j4+1)*256 + 8*l);
            #pragma unroll
            for (int jj=0;jj<4;jj++){
                unsigned u01 = (jj==0)?wa.x:(jj==1)?wa.z:(jj==2)?wb.x:wb.z;
                unsigned u23 = (jj==0)?wa.y:(jj==1)?wa.w:(jj==2)?wb.y:wb.w;
                float4 wv = cvt_w4(u01, u23);
                float xa0=f4get(xq0,jj), xa1=f4get(xq1,jj), xa2=f4get(xq2,jj), xa3=f4get(xq3,jj);
                h1[0][0]+=wv.x*xa0; h1[0][1]+=wv.y*xa0; h1[0][2]+=wv.z*xa0; h1[0][3]+=wv.w*xa0;
                h1[1][0]+=wv.x*xa1; h1[1][1]+=wv.y*xa1; h1[1][2]+=wv.z*xa1; h1[1][3]+=wv.w*xa1;
                h1[2][0]+=wv.x*xa2; h1[2][1]+=wv.y*xa2; h1[2][2]+=wv.z*xa2; h1[2][3]+=wv.w*xa2;
                h1[3][0]+=wv.x*xa3; h1[3][1]+=wv.y*xa3; h1[3][2]+=wv.z*xa3; h1[3][3]+=wv.w*xa3;
            }
        }
        __syncwarp();
        float ax1[4];
        {
            float bv1[4] = {FB1H[4*l], FB1H[4*l+1], FB1H[4*l+2], FB1H[4*l+3]};
            const float fb1h2 = SC[8];
            #pragma unroll
            for (int mm=0;mm<4;mm++){
                float n2o;
                blin_nl<4>(h1[mm], bv1, fb1h2, axagg[mm], true, ax1[mm], n2o);
                *(float4*)(S + mm*128 + 4*l) = make_float4(h1[mm][0], h1[mm][1], h1[mm][2], h1[mm][3]);
            }
        }
        __syncwarp();

        // ---- stage D2: h2 = blinear(h1, fw2, fb2), fp16 weights + Klein accumulation ----
        float h2a[4][4];
        #pragma unroll
        for (int mm=0;mm<4;mm++)
            #pragma unroll
            for (int c=0;c<4;c++) h2a[mm][c] = 0.f;
        #pragma unroll 2
        for (int j4=0;j4<32;j4++){
            float4 xq0 = *(const float4*)(S + 0*128 + j4*4);
            float4 xq1 = *(const float4*)(S + 1*128 + j4*4);
            float4 xq2 = *(const float4*)(S + 2*128 + j4*4);
            float4 xq3 = *(const float4*)(S + 3*128 + j4*4);
            uint4 wa = *(const uint4*)(HF2 + (2*j4+0)*256 + 8*l);
            uint4 wb = *(const uint4*)(HF2 + (2*j4+1)*256 + 8*l);
            #pragma unroll
            for (int jj=0;jj<4;jj++){
                unsigned u01 = (jj==0)?wa.x:(jj==1)?wa.z:(jj==2)?wb.x:wb.z;
                unsigned u23 = (jj==0)?wa.y:(jj==1)?wa.w:(jj==2)?wb.y:wb.w;
                float4 wv = cvt_w4(u01, u23);
                float xa0=f4get(xq0,jj), xa1=f4get(xq1,jj), xa2=f4get(xq2,jj), xa3=f4get(xq3,jj);
                h2a[0][0]+=wv.x*xa0; h2a[0][1]+=wv.y*xa0; h2a[0][2]+=wv.z*xa0; h2a[0][3]+=wv.w*xa0;
                h2a[1][0]+=wv.x*xa1; h2a[1][1]+=wv.y*xa1; h2a[1][2]+=wv.z*xa1; h2a[1][3]+=wv.w*xa1;
                h2a[2][0]+=wv.x*xa2; h2a[2][1]+=wv.y*xa2; h2a[2][2]+=wv.z*xa2; h2a[2][3]+=wv.w*xa2;
                h2a[3][0]+=wv.x*xa3; h2a[3][1]+=wv.y*xa3; h2a[3][2]+=wv.z*xa3; h2a[3][3]+=wv.w*xa3;
            }
        }
        {
            float bv2[4] = {FB2H[4*l], FB2H[4*l+1], FB2H[4*l+2], FB2H[4*l+3]};
            const float fb2h2 = SC[9];
            #pragma unroll
            for (int mm=0;mm<4;mm++){
                float axo, r2o;
                blin_nl<4>(h2a[mm], bv2, fb2h2, ax1[mm], false, axo, r2o);
                float fk  = __fdividef(2.0f, 1.0f + r2o);
                float kk2 = fk*fk*r2o;
                float lor = rsqrtf(fmaxf(1.0f - kk2, MINV));
                float cw  = S[SOFF_MASK + mm]*lor;
                float cf  = cw*fk;
                mden += cw;
                #pragma unroll
                for (int c=0;c<4;c++) mnum[c] += cf*h2a[mm][c];
            }
        }
        __syncwarp();
    }

    // ---- neighbor Klein midpoint -> mid (128-d) ----
    float imd = __fdividef(1.0f, fmaxf(mden, MINV));
    float mk4[4]; float s = 0.f;
    #pragma unroll
    for (int c=0;c<4;c++){ mk4[c] = mnum[c]*imd; s += mk4[c]*mk4[c]; }
    float kk2 = wred(s);
    float s2 = __fdividef(1.0f, 1.0f + sqrtf(fmaxf(1.0f - kk2, MINV)));
    float p2 = s2*s2*kk2;
    float spp = 1.0f;
    { float pn = sqrtf(fmaxf(p2, MINV));
      if (pn > MAXN){ spp = __fdividef(MAXN, pn); p2 = MAXN*MAXN; } }
    float cc = s2*spp;
    #pragma unroll
    for (int c=0;c<4;c++) mk4[c] *= cc;
    *(float4*)(S + 4*l) = make_float4(mk4[0], mk4[1], mk4[2], mk4[3]);
    float axmid;
    { float nn = sqrtf(fmaxf(p2, MINV)); axmid = __fdividef(artanh_c(nn), nn); }
    __syncwarp();

    // ---- tail E1: out1 = blinear(mid, gw1, gb1, relu) ----
    float g1v[2] = {0.f, 0.f};
    #pragma unroll 4
    for (int i4=0;i4<32;i4++){
        float4 xs = *(const float4*)(S + i4*4);
        float4 w0 = __ldg((const float4*)(gw1 + (2*l)*128 + i4*4));
        float4 w1 = __ldg((const float4*)(gw1 + (2*l+1)*128 + i4*4));
        g1v[0] += w0.x*xs.x + w0.y*xs.y + w0.z*xs.z + w0.w*xs.w;
        g1v[1] += w1.x*xs.x + w1.y*xs.y + w1.z*xs.z + w1.w*xs.w;
    }
    __syncwarp();
    float axo1, r2o1;
    {
        float bvg1[2] = {GB1H[2*l], GB1H[2*l+1]};
        blin_nl<2>(g1v, bvg1, SC[10], axmid, true, axo1, r2o1);
    }
    *(float2*)(S + 2*l) = make_float2(g1v[0], g1v[1]);
    __syncwarp();

    // ---- tail E2: out = blinear(out1, gw2, gb2) ----
    float g2v[2] = {0.f, 0.f};
    #pragma unroll 4
    for (int i4=0;i4<16;i4++){
        float4 xs = *(const float4*)(S + i4*4);
        float4 w0 = __ldg((const float4*)(gw2 + (2*l)*64 + i4*4));
        float4 w1 = __ldg((const float4*)(gw2 + (2*l+1)*64 + i4*4));
        g2v[0] += w0.x*xs.x + w0.y*xs.y + w0.z*xs.z + w0.w*xs.w;
        g2v[1] += w1.x*xs.x + w1.y*xs.y + w1.z*xs.z + w1.w*xs.w;
    }
    float axo2, r2o2;
    {
        float bvg2[2] = {GB2H[2*l], GB2H[2*l+1]};
        blin_nl<2>(g2v, bvg2, SC[11], axo1, false, axo2, r2o2);
    }
    *(float2*)(out + node*64 + 2*l) = make_float2(g2v[0], g2v[1]);
}

extern "C" void kernel_launch(void* const* d_in, const int* in_sizes, int n_in,
                              void* d_out, int out_size){
    const float* x       = (const float*)d_in[0];
    const int*   nei     = (const int*)  d_in[1];
    const float* neimask = (const float*)d_in[2];
    const float* kt      = (const float*)d_in[3];
    const float* lin_w   = (const float*)d_in[4];
    const float* lin_b   = (const float*)d_in[5];
    const float* fw1     = (const float*)d_in[6];
    const float* fb1     = (const float*)d_in[7];
    const float* fw2     = (const float*)d_in[8];
    const float* fb2     = (const float*)d_in[9];
    const float* gw1     = (const float*)d_in[10];
    const float* gb1     = (const float*)d_in[11];
    const float* gw2     = (const float*)d_in[12];
    const float* gb2     = (const float*)d_in[13];
    float* out = (float*)d_out;
    const int N = in_sizes[0]/64;

    cudaFuncSetAttribute(kp_main, cudaFuncAttributeMaxDynamicSharedMemorySize, SMEM_BYTES);
    prep_kernel<<<1, 256>>>(kt, lin_b, fb1, fb2, gb1, gb2);
    kp_main<<<(N + NWARP - 1)/NWARP, NTHR, SMEM_BYTES>>>(x, nei, neimask, lin_w, fw1, fw2, gw1, gw2, out, N);
}

// round 12
// speedup vs baseline: 1.1014x; 1.0348x over previous
#include <cuda_runtime.h>
#include <cuda_fp16.h>

#define FULLMASK 0xffffffffu
#define MINV 1e-12f
#define EPSV 1e-6f
#define MAXN (1.0f - 1e-5f)
#define KPI  (1.0f/0.66f)

#define NWARP 28
#define NTHR  (NWARP*32)

// shared layout (float offsets)
#define OFF_W4H   0            // fp16 packed lin_w: [2][32 rowpairs][256 halves]
#define OFF_FW1H  8192         // fp16 fw1T: [32 rowpairs][256 halves]
#define OFF_FW2H  12288        // fp16 fw2T: [64 rowpairs][256 halves]
#define OFF_CONST 20480        // 912 floats
#define OFF_STAGE 21392
#define WSTRIDE   800
#define SOFF_ST2  0            // 512: transposed 128-dim staging (h1 / tail)
#define SOFF_XT   512          // 256: transposed 64-dim staging (x / agg)
#define SOFF_WKM  768          // 16
#define SOFF_AARR 784          // 4
#define SOFF_MASK 788          // 4
#define SOFF_XK   792          // 4
#define SMEM_FLOATS (OFF_STAGE + NWARP*WSTRIDE)
#define SMEM_BYTES  (SMEM_FLOATS*4)

typedef unsigned long long u64t;

__device__ float g_const[1024];
// 0 klp[4][64], 256 hb[4][64], 512 fb1h[128], 640 fb2h[128], 768 gb1h[64], 832 gb2h[64], 896 scal[12]

__device__ __forceinline__ float wred(float v){
    v += __shfl_xor_sync(FULLMASK, v, 16);
    v += __shfl_xor_sync(FULLMASK, v, 8);
    v += __shfl_xor_sync(FULLMASK, v, 4);
    v += __shfl_xor_sync(FULLMASK, v, 2);
    v += __shfl_xor_sync(FULLMASK, v, 1);
    return v;
}
__device__ __forceinline__ float tanh_pos(float xx){
    float e = __expf(-2.0f*xx);
    return __fdividef(1.0f - e, 1.0f + e);
}
__device__ __forceinline__ float artanh_c(float xx){
    xx = fminf(fmaxf(xx, -1.0f + EPSV), 1.0f - EPSV);
    return 0.5f*__logf(__fdividef(1.0f + xx, 1.0f - xx));
}
// packed f32x2 helpers (Blackwell)
__device__ __forceinline__ u64t dup2(float x){
    u64t r; asm("mov.b64 %0, {%1, %1};" : "=l"(r) : "f"(x)); return r;
}
__device__ __forceinline__ void fma2(u64t& d, u64t a, u64t b){
    asm("fma.rn.f32x2 %0, %1, %2, %0;" : "+l"(d) : "l"(a), "l"(b));
}
__device__ __forceinline__ float2 unp(u64t v){
    float2 r; asm("mov.b64 {%0, %1}, %2;" : "=f"(r.x), "=f"(r.y) : "l"(v)); return r;
}

template<int V>
__device__ __forceinline__ void emap(const float* __restrict__ b, float* __restrict__ dst,
                                     float* __restrict__ n2dst, bool doproj){
    int l = threadIdx.x & 31;
    float u[V]; float s = 0.f;
    #pragma unroll
    for (int c=0;c<V;c++){ u[c] = b[V*l+c]; s += u[c]*u[c]; }
    float n2 = wred(s);
    float n  = sqrtf(fmaxf(n2, MINV));
    float f  = __fdividef(tanh_pos(n), n);
    float h2 = f*f*n2;
    if (doproj){
        float pn = sqrtf(fmaxf(h2, MINV));
        if (pn > MAXN){ f *= __fdividef(MAXN, pn); h2 = MAXN*MAXN; }
    }
    #pragma unroll
    for (int c=0;c<V;c++) dst[V*l+c] = f*u[c];
    if (l == 0) *n2dst = h2;
}

__global__ void prep_kernel(const float* __restrict__ kt, const float* __restrict__ lin_b,
                            const float* __restrict__ fb1, const float* __restrict__ fb2,
                            const float* __restrict__ gb1, const float* __restrict__ gb2){
    int w = threadIdx.x >> 5;
    if (w < 4){
        emap<2>(kt + w*64,    g_const + w*64,       g_const + 896 + w, false);
        emap<2>(lin_b + w*64, g_const + 256 + w*64, g_const + 900 + w, true);
    } else if (w == 4) emap<4>(fb1, g_const + 512, g_const + 904, true);
    else if (w == 5)   emap<4>(fb2, g_const + 640, g_const + 905, true);
    else if (w == 6)   emap<2>(gb1, g_const + 768, g_const + 906, true);
    else if (w == 7)   emap<2>(gb2, g_const + 832, g_const + 907, true);
}

template<int V>
__device__ __forceinline__ void blin_nl(float* h, const float* bvec, float b2,
                                        float ax_in, bool do_act,
                                        float& out_ax, float& out_n2){
    float s = 0.f;
    #pragma unroll
    for (int c=0;c<V;c++) s += h[c]*h[c];
    float mv2 = wred(s);
    float mvn = sqrtf(fmaxf(mv2, MINV));
    float fac = __fdividef(tanh_pos(mvn*ax_in), mvn);
    float f2  = fac*fac*mv2;
    { float pn = sqrtf(fmaxf(f2, MINV));
      if (pn > MAXN){ fac *= __fdividef(MAXN, pn); f2 = MAXN*MAXN; } }
    float mh = 0.f;
    #pragma unroll
    for (int c=0;c<V;c++) mh += h[c]*bvec[c];
    mh = wred(mh);
    float xy  = fac*mh;
    float A   = 1.0f + 2.0f*xy + b2;
    float B   = 1.0f - f2;
    float D   = fmaxf(1.0f + 2.0f*xy + f2*b2, MINV);
    float idn = __fdividef(1.0f, D);
    float r2  = (A*A*f2 + 2.0f*A*B*xy + B*B*b2)*idn*idn;
    float sp  = 1.0f;
    { float rn = sqrtf(fmaxf(r2, MINV));
      if (rn > MAXN){ sp = __fdividef(MAXN, rn); r2 = MAXN*MAXN; } }
    float cA = sp*idn*A*fac, cB = sp*idn*B;
    #pragma unroll
    for (int c=0;c<V;c++) h[c] = cA*h[c] + cB*bvec[c];
    if (do_act){
        float rn = sqrtf(fmaxf(r2, MINV));
        float lm = __fdividef(artanh_c(rn), rn);
        float t = 0.f;
        #pragma unroll
        for (int c=0;c<V;c++){ float u = fmaxf(h[c],0.f)*lm; h[c]=u; t += u*u; }
        float t2 = wred(t);
        float tn = sqrtf(fmaxf(t2, MINV));
        float ef = __fdividef(tanh_pos(tn), tn);
        float o2 = ef*ef*t2;
        float so = 1.0f;
        { float on = sqrtf(fmaxf(o2, MINV));
          if (on > MAXN){ so = __fdividef(MAXN, on); o2 = MAXN*MAXN; } }
        float cc = ef*so;
        #pragma unroll
        for (int c=0;c<V;c++) h[c] *= cc;
        r2 = o2;
    }
    out_n2 = r2;
    float nn = sqrtf(fmaxf(r2, MINV));
    out_ax = __fdividef(artanh_c(nn), nn);
}

__global__ void __launch_bounds__(NTHR, 1)
kp_main(const float* __restrict__ x, const int* __restrict__ nei,
        const float* __restrict__ neimask, const float* __restrict__ lin_w,
        const float* __restrict__ fw1, const float* __restrict__ fw2,
        const float* __restrict__ gw1, const float* __restrict__ gw2,
        float* __restrict__ out, int N)
{
    extern __shared__ float sm[];
    const int tid = threadIdx.x, wid = tid >> 5, l = tid & 31;

    __half* HW  = (__half*)(sm + OFF_W4H);
    __half* HF1 = (__half*)(sm + OFF_FW1H);
    __half* HF2 = (__half*)(sm + OFF_FW2H);

    // lin_w -> fp16: idx = p*8192 + j2*256 + lane*8 + r01*4 + kk*2 + oo
    for (int i = tid; i < 16384; i += NTHR){
        int p = i >> 13, rem = i & 8191, j2 = rem >> 8, q = rem & 255;
        int lane = q >> 3, c8 = q & 7, r01 = c8 >> 2, kk = (c8 >> 1) & 1, oo = c8 & 1;
        int row = 2*j2 + r01, k = 2*p + kk, o = 2*lane + oo;
        HW[i] = __float2half_rn(lin_w[k*4096 + o*64 + row]);
    }
    // fw1 -> fp16: idx = j2*256 + lane*8 + r01*4 + c ; o = 4*lane+c, row = 2*j2+r01
    for (int i = tid; i < 8192; i += NTHR){
        int j2 = i >> 8, q = i & 255, lane = q >> 3, c8 = q & 7, r01 = c8 >> 2, c = c8 & 3;
        int row = 2*j2 + r01, o = 4*lane + c;
        HF1[i] = __float2half_rn(fw1[o*64 + row]);
    }
    // fw2 -> fp16 (128 rows)
    for (int i = tid; i < 16384; i += NTHR){
        int j2 = i >> 8, q = i & 255, lane = q >> 3, c8 = q & 7, r01 = c8 >> 2, c = c8 & 3;
        int row = 2*j2 + r01, o = 4*lane + c;
        HF2[i] = __float2half_rn(fw2[o*128 + row]);
    }
    for (int i = tid; i < 908; i += NTHR) sm[OFF_CONST + i] = g_const[i];
    __syncthreads();

    const int node = blockIdx.x*NWARP + wid;
    if (node >= N) return;

    float* S   = sm + OFF_STAGE + wid*WSTRIDE;
    float* ST2 = S + SOFF_ST2;
    float* XT  = S + SOFF_XT;
    const float* KLP  = sm + OFF_CONST;
    const float* HB   = KLP + 256;
    const float* FB1H = KLP + 512;
    const float* FB2H = KLP + 640;
    const float* GB1H = KLP + 768;
    const float* GB2H = KLP + 832;
    const float* SC   = KLP + 896;

    // center point
    float2 xv = *(const float2*)(x + node*64 + 2*l);
    float x2 = wred(xv.x*xv.x + xv.y*xv.y);
    { float n = sqrtf(fmaxf(x2, MINV));
      if (n > MAXN){ float s = __fdividef(MAXN, n); xv.x*=s; xv.y*=s; x2 = MAXN*MAXN; } }

    // center-kernel dots -> scratch
    {
        float xk[4];
        #pragma unroll
        for (int k=0;k<4;k++){
            float2 kp = *(const float2*)(KLP + k*64 + 2*l);
            xk[k] = wred(xv.x*kp.x + xv.y*kp.y);
        }
        if (l == 0) *(float4*)(S + SOFF_XK) = make_float4(xk[0], xk[1], xk[2], xk[3]);
    }
    __syncwarp();

    float mnum[4] = {0.f,0.f,0.f,0.f};
    float mden = 0.f;

    for (int g = 0; g < 4; g++){
        // ---- stage A: gather/proj, transpose-stage x, lane-parallel KP weights ----
        float d_n2 = 0.f, d_xdn = 0.f, d_nk = 0.f;
        #pragma unroll
        for (int mm=0; mm<4; mm++){
            const int m = g*4 + mm;
            const int idx = __ldg(nei + node*16 + m);
            float2 v = *(const float2*)(x + idx*64 + 2*l);
            float n2 = wred(v.x*v.x + v.y*v.y);
            float nn = sqrtf(fmaxf(n2, MINV));
            if (nn > MAXN){ float s = __fdividef(MAXN, nn); v.x*=s; v.y*=s; n2 = MAXN*MAXN; }
            XT[(2*l+0)*4 + mm] = v.x;
            XT[(2*l+1)*4 + mm] = v.y;
            float xdn = wred(xv.x*v.x + xv.y*v.y);
            const bool quad = ((l>>2) == mm);
            if (quad){ d_n2 = n2; d_xdn = xdn; }
            #pragma unroll
            for (int k=0;k<4;k++){
                float2 kp = *(const float2*)(KLP + k*64 + 2*l);
                float nk = wred(v.x*kp.x + v.y*kp.y);
                if (quad && (l&3)==k) d_nk = nk;
            }
        }
        {   // lane-parallel chain: lane j = mm*4+k
            const int mmj = (l >> 2) & 3, kj = l & 3;
            float xkj   = S[SOFF_XK + kj];
            float klp2j = SC[kj];
            float a   = 1.0f - 2.0f*d_xdn + d_n2;
            float b   = 1.0f - x2;
            float den = fmaxf(1.0f - 2.0f*d_xdn + x2*d_n2, MINV);
            float idn = __fdividef(1.0f, den);
            float x02 = (a*a*x2 - 2.0f*a*b*d_xdn + b*b*d_n2)*idn*idn;
            float s0  = 1.0f;
            { float n0 = sqrtf(fmaxf(x02, MINV));
              if (n0 > MAXN){ s0 = __fdividef(MAXN, n0); x02 = MAXN*MAXN; } }
            float x0k = (-a*xkj + b*d_nk)*idn*s0;
            float A = 1.0f - 2.0f*x0k + klp2j;
            float B = 1.0f - x02;
            float D = fmaxf(1.0f - 2.0f*x0k + x02*klp2j, MINV);
            float iD = __fdividef(1.0f, D);
            float nsq = (A*A*x02 - 2.0f*A*B*x0k + B*B*klp2j)*iD*iD;
            float nd = sqrtf(fmaxf(nsq, MINV));
            float dd = 2.0f*artanh_c(nd);
            float wv = fmaxf(0.f, 1.0f - dd*KPI);
            float sw = wv + __shfl_xor_sync(FULLMASK, wv, 1);
            sw += __shfl_xor_sync(FULLMASK, sw, 2);
            float isw = __fdividef(1.0f, fmaxf(sw, MINV));
            if (l < 16){
                S[SOFF_WKM + l] = wv*isw;
                if (kj == 0){
                    float nn2 = sqrtf(fmaxf(d_n2, MINV));
                    S[SOFF_AARR + mmj] = __fdividef(artanh_c(nn2), nn2);
                    S[SOFF_MASK + mmj] = __ldg(neimask + node*16 + g*4 + mmj);
                }
            }
        }
        __syncwarp();

        // ---- stage B: two k-pair passes, packed f32x2 matvec ----
        float kn0[4], kn1[4], kdn[4];
        #pragma unroll
        for (int mm=0;mm<4;mm++){ kn0[mm]=0.f; kn1[mm]=0.f; kdn[mm]=0.f; }
        #pragma unroll 1
        for (int p=0;p<2;p++){
            u64t acc2[2][2][2];   // [kk][oo][pair]
            #pragma unroll
            for (int kk=0;kk<2;kk++)
                #pragma unroll
                for (int oo=0;oo<2;oo++)
                    #pragma unroll
                    for (int pr=0;pr<2;pr++) acc2[kk][oo][pr] = 0ull;
            #pragma unroll 2
            for (int j2=0;j2<32;j2++){
                ulonglong2 xe = *(const ulonglong2*)(XT + (2*j2+0)*4);
                ulonglong2 xo = *(const ulonglong2*)(XT + (2*j2+1)*4);
                uint4 w = *(const uint4*)(HW + p*8192 + j2*256 + 8*l);
                {   float2 f0 = __half22float2(*(const __half2*)&w.x);
                    float2 f1 = __half22float2(*(const __half2*)&w.y);
                    u64t w00=dup2(f0.x), w01=dup2(f0.y), w10=dup2(f1.x), w11=dup2(f1.y);
                    fma2(acc2[0][0][0], w00, xe.x); fma2(acc2[0][0][1], w00, xe.y);
                    fma2(acc2[0][1][0], w01, xe.x); fma2(acc2[0][1][1], w01, xe.y);
                    fma2(acc2[1][0][0], w10, xe.x); fma2(acc2[1][0][1], w10, xe.y);
                    fma2(acc2[1][1][0], w11, xe.x); fma2(acc2[1][1][1], w11, xe.y); }
                {   float2 f0 = __half22float2(*(const __half2*)&w.z);
                    float2 f1 = __half22float2(*(const __half2*)&w.w);
                    u64t w00=dup2(f0.x), w01=dup2(f0.y), w10=dup2(f1.x), w11=dup2(f1.y);
                    fma2(acc2[0][0][0], w00, xo.x); fma2(acc2[0][0][1], w00, xo.y);
                    fma2(acc2[0][1][0], w01, xo.x); fma2(acc2[0][1][1], w01, xo.y);
                    fma2(acc2[1][0][0], w10, xo.x); fma2(acc2[1][0][1], w10, xo.y);
                    fma2(acc2[1][1][0], w11, xo.x); fma2(acc2[1][1][1], w11, xo.y); }
            }
            // unpack acc: accf[kk][mm][oo]
            float accf[2][4][2];
            #pragma unroll
            for (int kk=0;kk<2;kk++)
                #pragma unroll
                for (int oo=0;oo<2;oo++)
                    #pragma unroll
                    for (int pr=0;pr<2;pr++){
                        float2 t = unp(acc2[kk][oo][pr]);
                        accf[kk][2*pr+0][oo] = t.x;
                        accf[kk][2*pr+1][oo] = t.y;
                    }
            // epilogue phase 1: reductions + lane deposits (lane j = kk*4+mm)
            float2 hbv0 = *(const float2*)(HB + (2*p+0)*64 + 2*l);
            float2 hbv1 = *(const float2*)(HB + (2*p+1)*64 + 2*l);
            float d_mx2 = 0.f, d_mh = 0.f;
            #pragma unroll
            for (int kk=0;kk<2;kk++){
                float2 hbv = kk ? hbv1 : hbv0;
                #pragma unroll
                for (int mm=0;mm<4;mm++){
                    float a0=accf[kk][mm][0], a1=accf[kk][mm][1];
                    float mx2 = wred(a0*a0 + a1*a1);
                    float mh  = wred(a0*hbv.x + a1*hbv.y);
                    if (l == kk*4+mm){ d_mx2 = mx2; d_mh = mh; }
                }
            }
            // epilogue phase 2: lane-parallel chain (lanes 0-7 meaningful)
            float c1, c2, cwv;
            {
                const int kkj = (l >> 2) & 1, mmj = l & 3;
                const int kj = 2*p + kkj;
                float aa   = S[SOFF_AARR + mmj];
                float hb2k = SC[4 + kj];
                float wkmv = S[SOFF_WKM + mmj*4 + kj];
                float mxn = sqrtf(fmaxf(d_mx2, MINV));
                float fac = __fdividef(tanh_pos(mxn*aa), mxn);
                float f2  = fac*fac*d_mx2;
                { float pn = sqrtf(fmaxf(f2, MINV));
                  if (pn > MAXN){ fac *= __fdividef(MAXN, pn); f2 = MAXN*MAXN; } }
                float xy = fac*d_mh;
                float A = 1.0f + 2.0f*xy + hb2k;
                float B = 1.0f - f2;
                float D = fmaxf(1.0f + 2.0f*xy + f2*hb2k, MINV);
                float iD = __fdividef(1.0f, D);
                float r2 = (A*A*f2 + 2.0f*A*B*xy + B*B*hb2k)*iD*iD;
                float sp = 1.0f;
                { float rn = sqrtf(fmaxf(r2, MINV));
                  if (rn > MAXN){ sp = __fdividef(MAXN, rn); r2 = MAXN*MAXN; } }
                float fk  = __fdividef(2.0f, 1.0f + r2);
                float kk2 = fk*fk*r2;
                float lor = rsqrtf(fmaxf(1.0f - kk2, MINV));
                cwv = wkmv*lor;
                float cf  = cwv*fk*sp*iD;
                c1 = cf*A*fac;
                c2 = cf*B;
            }
            // epilogue phase 3: broadcast + accumulate Klein sums
            #pragma unroll
            for (int kk=0;kk<2;kk++){
                float2 hbv = kk ? hbv1 : hbv0;
                #pragma unroll
                for (int mm=0;mm<4;mm++){
                    const int j = kk*4+mm;
                    float c1j = __shfl_sync(FULLMASK, c1, j);
                    float c2j = __shfl_sync(FULLMASK, c2, j);
                    float cwj = __shfl_sync(FULLMASK, cwv, j);
                    kn0[mm] += c1j*accf[kk][mm][0] + c2j*hbv.x;
                    kn1[mm] += c1j*accf[kk][mm][1] + c2j*hbv.y;
                    kdn[mm] += cwj;
                }
            }
        }
        __syncwarp();

        // ---- stage C: Klein midpoint normalize -> agg (transposed into XT) ----
        float axagg[4];
        #pragma unroll
        for (int mm=0;mm<4;mm++){
            float ikd = __fdividef(1.0f, fmaxf(kdn[mm], MINV));
            float k0 = kn0[mm]*ikd, k1 = kn1[mm]*ikd;
            float kk2 = wred(k0*k0 + k1*k1);
            float s2 = __fdividef(1.0f, 1.0f + sqrtf(fmaxf(1.0f - kk2, MINV)));
            float p0 = s2*k0, p1 = s2*k1;
            float p2 = s2*s2*kk2;
            float spp = 1.0f;
            { float pn = sqrtf(fmaxf(p2, MINV));
              if (pn > MAXN){ spp = __fdividef(MAXN, pn); p2 = MAXN*MAXN; } }
            p0 *= spp; p1 *= spp;
            { float nn = sqrtf(fmaxf(p2, MINV)); axagg[mm] = __fdividef(artanh_c(nn), nn); }
            XT[(2*l+0)*4 + mm] = p0;
            XT[(2*l+1)*4 + mm] = p1;
        }
        __syncwarp();

        // ---- stage D1: h1 = blinear(agg, fw1, fb1, relu), packed matvec ----
        u64t h1p[4][2];   // [c][pair]
        #pragma unroll
        for (int c=0;c<4;c++){ h1p[c][0]=0ull; h1p[c][1]=0ull; }
        #pragma unroll 2
        for (int j2=0;j2<32;j2++){
            ulonglong2 xe = *(const ulonglong2*)(XT + (2*j2+0)*4);
            ulonglong2 xo = *(const ulonglong2*)(XT + (2*j2+1)*4);
            uint4 w = *(const uint4*)(HF1 + j2*256 + 8*l);
            {   float2 f0 = __half22float2(*(const __half2*)&w.x);
                float2 f1 = __half22float2(*(const __half2*)&w.y);
                u64t wc0=dup2(f0.x), wc1=dup2(f0.y), wc2=dup2(f1.x), wc3=dup2(f1.y);
                fma2(h1p[0][0], wc0, xe.x); fma2(h1p[0][1], wc0, xe.y);
                fma2(h1p[1][0], wc1, xe.x); fma2(h1p[1][1], wc1, xe.y);
                fma2(h1p[2][0], wc2, xe.x); fma2(h1p[2][1], wc2, xe.y);
                fma2(h1p[3][0], wc3, xe.x); fma2(h1p[3][1], wc3, xe.y); }
            {   float2 f0 = __half22float2(*(const __half2*)&w.z);
                float2 f1 = __half22float2(*(const __half2*)&w.w);
                u64t wc0=dup2(f0.x), wc1=dup2(f0.y), wc2=dup2(f1.x), wc3=dup2(f1.y);
                fma2(h1p[0][0], wc0, xo.x); fma2(h1p[0][1], wc0, xo.y);
                fma2(h1p[1][0], wc1, xo.x); fma2(h1p[1][1], wc1, xo.y);
                fma2(h1p[2][0], wc2, xo.x); fma2(h1p[2][1], wc2, xo.y);
                fma2(h1p[3][0], wc3, xo.x); fma2(h1p[3][1], wc3, xo.y); }
        }
        float h1[4][4];
        #pragma unroll
        for (int c=0;c<4;c++)
            #pragma unroll
            for (int pr=0;pr<2;pr++){
                float2 t = unp(h1p[c][pr]);
                h1[2*pr+0][c] = t.x;
                h1[2*pr+1][c] = t.y;
            }
        __syncwarp();
        float ax1[4];
        {
            float bv1[4] = {FB1H[4*l], FB1H[4*l+1], FB1H[4*l+2], FB1H[4*l+3]};
            const float fb1h2 = SC[8];
            #pragma unroll
            for (int mm=0;mm<4;mm++){
                float n2o;
                blin_nl<4>(h1[mm], bv1, fb1h2, axagg[mm], true, ax1[mm], n2o);
            }
        }
        #pragma unroll
        for (int c=0;c<4;c++)
            *(float4*)(ST2 + (4*l+c)*4) = make_float4(h1[0][c], h1[1][c], h1[2][c], h1[3][c]);
        __syncwarp();

        // ---- stage D2: h2 = blinear(h1, fw2, fb2), packed matvec + Klein accumulation ----
        u64t h2p[4][2];
        #pragma unroll
        for (int c=0;c<4;c++){ h2p[c][0]=0ull; h2p[c][1]=0ull; }
        #pragma unroll 2
        for (int j2=0;j2<64;j2++){
            ulonglong2 xe = *(const ulonglong2*)(ST2 + (2*j2+0)*4);
            ulonglong2 xo = *(const ulonglong2*)(ST2 + (2*j2+1)*4);
            uint4 w = *(const uint4*)(HF2 + j2*256 + 8*l);
            {   float2 f0 = __half22float2(*(const __half2*)&w.x);
                float2 f1 = __half22float2(*(const __half2*)&w.y);
                u64t wc0=dup2(f0.x), wc1=dup2(f0.y), wc2=dup2(f1.x), wc3=dup2(f1.y);
                fma2(h2p[0][0], wc0, xe.x); fma2(h2p[0][1], wc0, xe.y);
                fma2(h2p[1][0], wc1, xe.x); fma2(h2p[1][1], wc1, xe.y);
                fma2(h2p[2][0], wc2, xe.x); fma2(h2p[2][1], wc2, xe.y);
                fma2(h2p[3][0], wc3, xe.x); fma2(h2p[3][1], wc3, xe.y); }
            {   float2 f0 = __half22float2(*(const __half2*)&w.z);
                float2 f1 = __half22float2(*(const __half2*)&w.w);
                u64t wc0=dup2(f0.x), wc1=dup2(f0.y), wc2=dup2(f1.x), wc3=dup2(f1.y);
                fma2(h2p[0][0], wc0, xo.x); fma2(h2p[0][1], wc0, xo.y);
                fma2(h2p[1][0], wc1, xo.x); fma2(h2p[1][1], wc1, xo.y);
                fma2(h2p[2][0], wc2, xo.x); fma2(h2p[2][1], wc2, xo.y);
                fma2(h2p[3][0], wc3, xo.x); fma2(h2p[3][1], wc3, xo.y); }
        }
        float h2a[4][4];
        #pragma unroll
        for (int c=0;c<4;c++)
            #pragma unroll
            for (int pr=0;pr<2;pr++){
                float2 t = unp(h2p[c][pr]);
                h2a[2*pr+0][c] = t.x;
                h2a[2*pr+1][c] = t.y;
            }
        {
            float bv2[4] = {FB2H[4*l], FB2H[4*l+1], FB2H[4*l+2], FB2H[4*l+3]};
            const float fb2h2 = SC[9];
            #pragma unroll
            for (int mm=0;mm<4;mm++){
                float axo, r2o;
                blin_nl<4>(h2a[mm], bv2, fb2h2, ax1[mm], false, axo, r2o);
                float fk  = __fdividef(2.0f, 1.0f + r2o);
                float kk2 = fk*fk*r2o;
                float lor = rsqrtf(fmaxf(1.0f - kk2, MINV));
                float cw  = S[SOFF_MASK + mm]*lor;
                float cf  = cw*fk;
                mden += cw;
                #pragma unroll
                for (int c=0;c<4;c++) mnum[c] += cf*h2a[mm][c];
            }
        }
        __syncwarp();
    }

    // ---- neighbor Klein midpoint -> mid (128-d) ----
    float imd = __fdividef(1.0f, fmaxf(mden, MINV));
    float mk4[4]; float s = 0.f;
    #pragma unroll
    for (int c=0;c<4;c++){ mk4[c] = mnum[c]*imd; s += mk4[c]*mk4[c]; }
    float kk2 = wred(s);
    float s2 = __fdividef(1.0f, 1.0f + sqrtf(fmaxf(1.0f - kk2, MINV)));
    float p2 = s2*s2*kk2;
    float spp = 1.0f;
    { float pn = sqrtf(fmaxf(p2, MINV));
      if (pn > MAXN){ spp = __fdividef(MAXN, pn); p2 = MAXN*MAXN; } }
    float cc = s2*spp;
    #pragma unroll
    for (int c=0;c<4;c++) mk4[c] *= cc;
    *(float4*)(ST2 + 4*l) = make_float4(mk4[0], mk4[1], mk4[2], mk4[3]);
    float axmid;
    { float nn = sqrtf(fmaxf(p2, MINV)); axmid = __fdividef(artanh_c(nn), nn); }
    __syncwarp();

    // ---- tail E1: out1 = blinear(mid, gw1, gb1, relu) ----
    float g1v[2] = {0.f, 0.f};
    #pragma unroll 4
    for (int i4=0;i4<32;i4++){
        float4 xs = *(const float4*)(ST2 + i4*4);
        float4 w0 = __ldg((const float4*)(gw1 + (2*l)*128 + i4*4));
        float4 w1 = __ldg((const float4*)(gw1 + (2*l+1)*128 + i4*4));
        g1v[0] += w0.x*xs.x + w0.y*xs.y + w0.z*xs.z + w0.w*xs.w;
        g1v[1] += w1.x*xs.x + w1.y*xs.y + w1.z*xs.z + w1.w*xs.w;
    }
    __syncwarp();
    float axo1, r2o1;
    {
        float bvg1[2] = {GB1H[2*l], GB1H[2*l+1]};
        blin_nl<2>(g1v, bvg1, SC[10], axmid, true, axo1, r2o1);
    }
    *(float2*)(ST2 + 2*l) = make_float2(g1v[0], g1v[1]);
    __syncwarp();

    // ---- tail E2: out = blinear(out1, gw2, gb2) ----
    float g2v[2] = {0.f, 0.f};
    #pragma unroll 4
    for (int i4=0;i4<16;i4++){
        float4 xs = *(const float4*)(ST2 + i4*4);
        float4 w0 = __ldg((const float4*)(gw2 + (2*l)*64 + i4*4));
        float4 w1 = __ldg((const float4*)(gw2 + (2*l+1)*64 + i4*4));
        g2v[0] += w0.x*xs.x + w0.y*xs.y + w0.z*xs.z + w0.w*xs.w;
        g2v[1] += w1.x*xs.x + w1.y*xs.y + w1.z*xs.z + w1.w*xs.w;
    }
    float axo2, r2o2;
    {
        float bvg2[2] = {GB2H[2*l], GB2H[2*l+1]};
        blin_nl<2>(g2v, bvg2, SC[11], axo1, false, axo2, r2o2);
    }
    *(float2*)(out + node*64 + 2*l) = make_float2(g2v[0], g2v[1]);
}

extern "C" void kernel_launch(void* const* d_in, const int* in_sizes, int n_in,
                              void* d_out, int out_size){
    const float* x       = (const float*)d_in[0];
    const int*   nei     = (const int*)  d_in[1];
    const float* neimask = (const float*)d_in[2];
    const float* kt      = (const float*)d_in[3];
    const float* lin_w   = (const float*)d_in[4];
    const float* lin_b   = (const float*)d_in[5];
    const float* fw1     = (const float*)d_in[6];
    const float* fb1     = (const float*)d_in[7];
    const float* fw2     = (const float*)d_in[8];
    const float* fb2     = (const float*)d_in[9];
    const float* gw1     = (const float*)d_in[10];
    const float* gb1     = (const float*)d_in[11];
    const float* gw2     = (const float*)d_in[12];
    const float* gb2     = (const float*)d_in[13];
    float* out = (float*)d_out;
    const int N = in_sizes[0]/64;

    cudaFuncSetAttribute(kp_main, cudaFuncAttributeMaxDynamicSharedMemorySize, SMEM_BYTES);
    prep_kernel<<<1, 256>>>(kt, lin_b, fb1, fb2, gb1, gb2);
    kp_main<<<(N + NWARP - 1)/NWARP, NTHR, SMEM_BYTES>>>(x, nei, neimask, lin_w, fw1, fw2, gw1, gw2, out, N);
}

// round 14
// speedup vs baseline: 1.1181x; 1.0151x over previous
#include <cuda_runtime.h>
#include <cuda_fp16.h>
#include <cstdint>

#define FULLMASK 0xffffffffu
#define MINV 1e-12f
#define EPSV 1e-6f
#define MAXN (1.0f - 1e-5f)
#define KPI  (1.0f/0.66f)

#define NWARP 28
#define NTHR  (NWARP*32)

// shared layout (float offsets)
#define OFF_W4H   0            // fp16 packed lin_w
#define OFF_FW1H  8192         // fp16 fw1T
#define OFF_FW2H  12288        // fp16 fw2T
#define OFF_CONST 20480        // 912 floats
#define OFF_STAGE 21392
#define WSTRIDE   1056
#define SOFF_ST2  0            // 512: transposed 128-dim staging
#define SOFF_XT   512          // 256: transposed 64-dim staging
#define SOFF_WKM  768          // 16
#define SOFF_AARR 784          // 4
#define SOFF_MASK 788          // 4
#define SOFF_XK   792          // 4
#define SOFF_PB   800          // 256: neighbor prefetch buffer [4][64]
#define SMEM_FLOATS (OFF_STAGE + NWARP*WSTRIDE)
#define SMEM_BYTES  (SMEM_FLOATS*4)

typedef unsigned long long u64t;

__device__ float g_const[1024];
// 0 klp[4][64], 256 hb[4][64], 512 fb1h[128], 640 fb2h[128], 768 gb1h[64], 832 gb2h[64], 896 scal[12]

__device__ __forceinline__ float wred(float v){
    v += __shfl_xor_sync(FULLMASK, v, 16);
    v += __shfl_xor_sync(FULLMASK, v, 8);
    v += __shfl_xor_sync(FULLMASK, v, 4);
    v += __shfl_xor_sync(FULLMASK, v, 2);
    v += __shfl_xor_sync(FULLMASK, v, 1);
    return v;
}
__device__ __forceinline__ float tanh_pos(float xx){
    float e = __expf(-2.0f*xx);
    return __fdividef(1.0f - e, 1.0f + e);
}
__device__ __forceinline__ float artanh_c(float xx){
    xx = fminf(fmaxf(xx, -1.0f + EPSV), 1.0f - EPSV);
    return 0.5f*__logf(__fdividef(1.0f + xx, 1.0f - xx));
}
// packed f32x2 helpers
__device__ __forceinline__ u64t dup2(float x){
    u64t r; asm("mov.b64 %0, {%1, %1};" : "=l"(r) : "f"(x)); return r;
}
__device__ __forceinline__ void fma2(u64t& d, u64t a, u64t b){
    asm("fma.rn.f32x2 %0, %1, %2, %0;" : "+l"(d) : "l"(a), "l"(b));
}
__device__ __forceinline__ float2 unp(u64t v){
    float2 r; asm("mov.b64 {%0, %1}, %2;" : "=f"(r.x), "=f"(r.y) : "l"(v)); return r;
}
// cp.async 8-byte prefetch
__device__ __forceinline__ void cpa8(uint32_t saddr, const void* g){
    asm volatile("cp.async.ca.shared.global [%0], [%1], 8;" :: "r"(saddr), "l"(g));
}
#define CP_COMMIT() asm volatile("cp.async.commit_group;")
#define CP_WAIT0()  asm volatile("cp.async.wait_group 0;")

template<int V>
__device__ __forceinline__ void emap(const float* __restrict__ b, float* __restrict__ dst,
                                     float* __restrict__ n2dst, bool doproj){
    int l = threadIdx.x & 31;
    float u[V]; float s = 0.f;
    #pragma unroll
    for (int c=0;c<V;c++){ u[c] = b[V*l+c]; s += u[c]*u[c]; }
    float n2 = wred(s);
    float n  = sqrtf(fmaxf(n2, MINV));
    float f  = __fdividef(tanh_pos(n), n);
    float h2 = f*f*n2;
    if (doproj){
        float pn = sqrtf(fmaxf(h2, MINV));
        if (pn > MAXN){ f *= __fdividef(MAXN, pn); h2 = MAXN*MAXN; }
    }
    #pragma unroll
    for (int c=0;c<V;c++) dst[V*l+c] = f*u[c];
    if (l == 0) *n2dst = h2;
}

__global__ void prep_kernel(const float* __restrict__ kt, const float* __restrict__ lin_b,
                            const float* __restrict__ fb1, const float* __restrict__ fb2,
                            const float* __restrict__ gb1, const float* __restrict__ gb2){
    int w = threadIdx.x >> 5;
    if (w < 4){
        emap<2>(kt + w*64,    g_const + w*64,       g_const + 896 + w, false);
        emap<2>(lin_b + w*64, g_const + 256 + w*64, g_const + 900 + w, true);
    } else if (w == 4) emap<4>(fb1, g_const + 512, g_const + 904, true);
    else if (w == 5)   emap<4>(fb2, g_const + 640, g_const + 905, true);
    else if (w == 6)   emap<2>(gb1, g_const + 768, g_const + 906, true);
    else if (w == 7)   emap<2>(gb2, g_const + 832, g_const + 907, true);
}

template<int V>
__device__ __forceinline__ void blin_nl(float* h, const float* bvec, float b2,
                                        float ax_in, bool do_act,
                                        float& out_ax, float& out_n2){
    float s = 0.f;
    #pragma unroll
    for (int c=0;c<V;c++) s += h[c]*h[c];
    float mv2 = wred(s);
    float mvn = sqrtf(fmaxf(mv2, MINV));
    float fac = __fdividef(tanh_pos(mvn*ax_in), mvn);
    float f2  = fac*fac*mv2;
    { float pn = sqrtf(fmaxf(f2, MINV));
      if (pn > MAXN){ fac *= __fdividef(MAXN, pn); f2 = MAXN*MAXN; } }
    float mh = 0.f;
    #pragma unroll
    for (int c=0;c<V;c++) mh += h[c]*bvec[c];
    mh = wred(mh);
    float xy  = fac*mh;
    float A   = 1.0f + 2.0f*xy + b2;
    float B   = 1.0f - f2;
    float D   = fmaxf(1.0f + 2.0f*xy + f2*b2, MINV);
    float idn = __fdividef(1.0f, D);
    float r2  = (A*A*f2 + 2.0f*A*B*xy + B*B*b2)*idn*idn;
    float sp  = 1.0f;
    { float rn = sqrtf(fmaxf(r2, MINV));
      if (rn > MAXN){ sp = __fdividef(MAXN, rn); r2 = MAXN*MAXN; } }
    float cA = sp*idn*A*fac, cB = sp*idn*B;
    #pragma unroll
    for (int c=0;c<V;c++) h[c] = cA*h[c] + cB*bvec[c];
    if (do_act){
        float rn = sqrtf(fmaxf(r2, MINV));
        float lm = __fdividef(artanh_c(rn), rn);
        float t = 0.f;
        #pragma unroll
        for (int c=0;c<V;c++){ float u = fmaxf(h[c],0.f)*lm; h[c]=u; t += u*u; }
        float t2 = wred(t);
        float tn = sqrtf(fmaxf(t2, MINV));
        float ef = __fdividef(tanh_pos(tn), tn);
        float o2 = ef*ef*t2;
        float so = 1.0f;
        { float on = sqrtf(fmaxf(o2, MINV));
          if (on > MAXN){ so = __fdividef(MAXN, on); o2 = MAXN*MAXN; } }
        float cc = ef*so;
        #pragma unroll
        for (int c=0;c<V;c++) h[c] *= cc;
        r2 = o2;
    }
    out_n2 = r2;
    float nn = sqrtf(fmaxf(r2, MINV));
    out_ax = __fdividef(artanh_c(nn), nn);
}

__global__ void __launch_bounds__(NTHR, 1)
kp_main(const float* __restrict__ x, const int* __restrict__ nei,
        const float* __restrict__ neimask, const float* __restrict__ lin_w,
        const float* __restrict__ fw1, const float* __restrict__ fw2,
        const float* __restrict__ gw1, const float* __restrict__ gw2,
        float* __restrict__ out, int N)
{
    extern __shared__ float sm[];
    const int tid = threadIdx.x, wid = tid >> 5, l = tid & 31;

    __half* HW  = (__half*)(sm + OFF_W4H);
    __half* HF1 = (__half*)(sm + OFF_FW1H);
    __half* HF2 = (__half*)(sm + OFF_FW2H);

    for (int i = tid; i < 16384; i += NTHR){
        int p = i >> 13, rem = i & 8191, j2 = rem >> 8, q = rem & 255;
        int lane = q >> 3, c8 = q & 7, r01 = c8 >> 2, kk = (c8 >> 1) & 1, oo = c8 & 1;
        int row = 2*j2 + r01, k = 2*p + kk, o = 2*lane + oo;
        HW[i] = __float2half_rn(lin_w[k*4096 + o*64 + row]);
    }
    for (int i = tid; i < 8192; i += NTHR){
        int j2 = i >> 8, q = i & 255, lane = q >> 3, c8 = q & 7, r01 = c8 >> 2, c = c8 & 3;
        int row = 2*j2 + r01, o = 4*lane + c;
        HF1[i] = __float2half_rn(fw1[o*64 + row]);
    }
    for (int i = tid; i < 16384; i += NTHR){
        int j2 = i >> 8, q = i & 255, lane = q >> 3, c8 = q & 7, r01 = c8 >> 2, c = c8 & 3;
        int row = 2*j2 + r01, o = 4*lane + c;
        HF2[i] = __float2half_rn(fw2[o*128 + row]);
    }
    for (int i = tid; i < 908; i += NTHR) sm[OFF_CONST + i] = g_const[i];
    __syncthreads();

    const int node = blockIdx.x*NWARP + wid;
    if (node >= N) return;

    float* S   = sm + OFF_STAGE + wid*WSTRIDE;
    float* ST2 = S + SOFF_ST2;
    float* XT  = S + SOFF_XT;
    float* PB  = S + SOFF_PB;
    const float* KLP  = sm + OFF_CONST;
    const float* HB   = KLP + 256;
    const float* FB1H = KLP + 512;
    const float* FB2H = KLP + 640;
    const float* GB1H = KLP + 768;
    const float* GB2H = KLP + 832;
    const float* SC   = KLP + 896;

    // kick off group-0 neighbor prefetch (overlaps center-point setup)
    {
        #pragma unroll
        for (int mm=0;mm<4;mm++){
            int idx = __ldg(nei + node*16 + mm);
            uint32_t dst = (uint32_t)__cvta_generic_to_shared(PB + mm*64 + 2*l);
            cpa8(dst, x + (size_t)idx*64 + 2*l);
        }
        CP_COMMIT();
    }

    // center point
    float2 xv = *(const float2*)(x + node*64 + 2*l);
    float x2 = wred(xv.x*xv.x + xv.y*xv.y);
    { float n = sqrtf(fmaxf(x2, MINV));
      if (n > MAXN){ float s = __fdividef(MAXN, n); xv.x*=s; xv.y*=s; x2 = MAXN*MAXN; } }

    // center-kernel dots -> scratch
    {
        float xk[4];
        #pragma unroll
        for (int k=0;k<4;k++){
            float2 kp = *(const float2*)(KLP + k*64 + 2*l);
            xk[k] = wred(xv.x*kp.x + xv.y*kp.y);
        }
        if (l == 0) *(float4*)(S + SOFF_XK) = make_float4(xk[0], xk[1], xk[2], xk[3]);
    }
    __syncwarp();

    float mnum[4] = {0.f,0.f,0.f,0.f};
    float mden = 0.f;

    for (int g = 0; g < 4; g++){
        CP_WAIT0();
        __syncwarp();

        // ---- stage A: read prefetched neighbors, proj, transpose-stage, KP weights ----
        float d_n2 = 0.f, d_xdn = 0.f, d_nk = 0.f;
        #pragma unroll
        for (int mm=0; mm<4; mm++){
            float2 v = *(const float2*)(PB + mm*64 + 2*l);
            float n2 = wred(v.x*v.x + v.y*v.y);
            float nn = sqrtf(fmaxf(n2, MINV));
            if (nn > MAXN){ float s = __fdividef(MAXN, nn); v.x*=s; v.y*=s; n2 = MAXN*MAXN; }
            XT[(2*l+0)*4 + mm] = v.x;
            XT[(2*l+1)*4 + mm] = v.y;
            float xdn = wred(xv.x*v.x + xv.y*v.y);
            const bool quad = ((l>>2) == mm);
            if (quad){ d_n2 = n2; d_xdn = xdn; }
            #pragma unroll
            for (int k=0;k<4;k++){
                float2 kp = *(const float2*)(KLP + k*64 + 2*l);
                float nk = wred(v.x*kp.x + v.y*kp.y);
                if (quad && (l&3)==k) d_nk = nk;
            }
        }
        __syncwarp();
        // issue next group's prefetch now; lands during stages B-D
        if (g < 3){
            #pragma unroll
            for (int mm=0;mm<4;mm++){
                int idx = __ldg(nei + node*16 + (g+1)*4 + mm);
                uint32_t dst = (uint32_t)__cvta_generic_to_shared(PB + mm*64 + 2*l);
                cpa8(dst, x + (size_t)idx*64 + 2*l);
            }
            CP_COMMIT();
        }
        {   // lane-parallel chain: lane j = mm*4+k
            const int mmj = (l >> 2) & 3, kj = l & 3;
            float xkj   = S[SOFF_XK + kj];
            float klp2j = SC[kj];
            float a   = 1.0f - 2.0f*d_xdn + d_n2;
            float b   = 1.0f - x2;
            float den = fmaxf(1.0f - 2.0f*d_xdn + x2*d_n2, MINV);
            float idn = __fdividef(1.0f, den);
            float x02 = (a*a*x2 - 2.0f*a*b*d_xdn + b*b*d_n2)*idn*idn;
            float s0  = 1.0f;
            { float n0 = sqrtf(fmaxf(x02, MINV));
              if (n0 > MAXN){ s0 = __fdividef(MAXN, n0); x02 = MAXN*MAXN; } }
            float x0k = (-a*xkj + b*d_nk)*idn*s0;
            float A = 1.0f - 2.0f*x0k + klp2j;
            float B = 1.0f - x02;
            float D = fmaxf(1.0f - 2.0f*x0k + x02*klp2j, MINV);
            float iD = __fdividef(1.0f, D);
            float nsq = (A*A*x02 - 2.0f*A*B*x0k + B*B*klp2j)*iD*iD;
            float nd = sqrtf(fmaxf(nsq, MINV));
            float dd = 2.0f*artanh_c(nd);
            float wv = fmaxf(0.f, 1.0f - dd*KPI);
            float sw = wv + __shfl_xor_sync(FULLMASK, wv, 1);
            sw += __shfl_xor_sync(FULLMASK, sw, 2);
            float isw = __fdividef(1.0f, fmaxf(sw, MINV));
            if (l < 16){
                S[SOFF_WKM + l] = wv*isw;
                if (kj == 0){
                    float nn2 = sqrtf(fmaxf(d_n2, MINV));
                    S[SOFF_AARR + mmj] = __fdividef(artanh_c(nn2), nn2);
                    S[SOFF_MASK + mmj] = __ldg(neimask + node*16 + g*4 + mmj);
                }
            }
        }
        __syncwarp();

        // ---- stage B: two k-pair passes, packed f32x2 matvec ----
        float kn0[4], kn1[4], kdn[4];
        #pragma unroll
        for (int mm=0;mm<4;mm++){ kn0[mm]=0.f; kn1[mm]=0.f; kdn[mm]=0.f; }
        #pragma unroll 1
        for (int p=0;p<2;p++){
            u64t acc2[2][2][2];   // [kk][oo][pair]
            #pragma unroll
            for (int kk=0;kk<2;kk++)
                #pragma unroll
                for (int oo=0;oo<2;oo++)
                    #pragma unroll
                    for (int pr=0;pr<2;pr++) acc2[kk][oo][pr] = 0ull;
            #pragma unroll 2
            for (int j2=0;j2<32;j2++){
                ulonglong2 xe = *(const ulonglong2*)(XT + (2*j2+0)*4);
                ulonglong2 xo = *(const ulonglong2*)(XT + (2*j2+1)*4);
                uint4 w = *(const uint4*)(HW + p*8192 + j2*256 + 8*l);
                {   float2 f0 = __half22float2(*(const __half2*)&w.x);
                    float2 f1 = __half22float2(*(const __half2*)&w.y);
                    u64t w00=dup2(f0.x), w01=dup2(f0.y), w10=dup2(f1.x), w11=dup2(f1.y);
                    fma2(acc2[0][0][0], w00, xe.x); fma2(acc2[0][0][1], w00, xe.y);
                    fma2(acc2[0][1][0], w01, xe.x); fma2(acc2[0][1][1], w01, xe.y);
                    fma2(acc2[1][0][0], w10, xe.x); fma2(acc2[1][0][1], w10, xe.y);
                    fma2(acc2[1][1][0], w11, xe.x); fma2(acc2[1][1][1], w11, xe.y); }
                {   float2 f0 = __half22float2(*(const __half2*)&w.z);
                    float2 f1 = __half22float2(*(const __half2*)&w.w);
                    u64t w00=dup2(f0.x), w01=dup2(f0.y), w10=dup2(f1.x), w11=dup2(f1.y);
                    fma2(acc2[0][0][0], w00, xo.x); fma2(acc2[0][0][1], w00, xo.y);
                    fma2(acc2[0][1][0], w01, xo.x); fma2(acc2[0][1][1], w01, xo.y);
                    fma2(acc2[1][0][0], w10, xo.x); fma2(acc2[1][0][1], w10, xo.y);
                    fma2(acc2[1][1][0], w11, xo.x); fma2(acc2[1][1][1], w11, xo.y); }
            }
            float accf[2][4][2];
            #pragma unroll
            for (int kk=0;kk<2;kk++)
                #pragma unroll
                for (int oo=0;oo<2;oo++)
                    #pragma unroll
                    for (int pr=0;pr<2;pr++){
                        float2 t = unp(acc2[kk][oo][pr]);
                        accf[kk][2*pr+0][oo] = t.x;
                        accf[kk][2*pr+1][oo] = t.y;
                    }
            float2 hbv0 = *(const float2*)(HB + (2*p+0)*64 + 2*l);
            float2 hbv1 = *(const float2*)(HB + (2*p+1)*64 + 2*l);
            float d_mx2 = 0.f, d_mh = 0.f;
            #pragma unroll
            for (int kk=0;kk<2;kk++){
                float2 hbv = kk ? hbv1 : hbv0;
                #pragma unroll
                for (int mm=0;mm<4;mm++){
                    float a0=accf[kk][mm][0], a1=accf[kk][mm][1];
                    float mx2 = wred(a0*a0 + a1*a1);
                    float mh  = wred(a0*hbv.x + a1*hbv.y);
                    if (l == kk*4+mm){ d_mx2 = mx2; d_mh = mh; }
                }
            }
            float c1, c2, cwv;
            {
                const int kkj = (l >> 2) & 1, mmj = l & 3;
                const int kj = 2*p + kkj;
                float aa   = S[SOFF_AARR + mmj];
                float hb2k = SC[4 + kj];
                float wkmv = S[SOFF_WKM + mmj*4 + kj];
                float mxn = sqrtf(fmaxf(d_mx2, MINV));
                float fac = __fdividef(tanh_pos(mxn*aa), mxn);
                float f2  = fac*fac*d_mx2;
                { float pn = sqrtf(fmaxf(f2, MINV));
                  if (pn > MAXN){ fac *= __fdividef(MAXN, pn); f2 = MAXN*MAXN; } }
                float xy = fac*d_mh;
                float A = 1.0f + 2.0f*xy + hb2k;
                float B = 1.0f - f2;
                float D = fmaxf(1.0f + 2.0f*xy + f2*hb2k, MINV);
                float iD = __fdividef(1.0f, D);
                float r2 = (A*A*f2 + 2.0f*A*B*xy + B*B*hb2k)*iD*iD;
                float sp = 1.0f;
                { float rn = sqrtf(fmaxf(r2, MINV));
                  if (rn > MAXN){ sp = __fdividef(MAXN, rn); r2 = MAXN*MAXN; } }
                float fk  = __fdividef(2.0f, 1.0f + r2);
                float kk2 = fk*fk*r2;
                float lor = rsqrtf(fmaxf(1.0f - kk2, MINV));
                cwv = wkmv*lor;
                float cf  = cwv*fk*sp*iD;
                c1 = cf*A*fac;
                c2 = cf*B;
            }
            #pragma unroll
            for (int kk=0;kk<2;kk++){
                float2 hbv = kk ? hbv1 : hbv0;
                #pragma unroll
                for (int mm=0;mm<4;mm++){
                    const int j = kk*4+mm;
                    float c1j = __shfl_sync(FULLMASK, c1, j);
                    float c2j = __shfl_sync(FULLMASK, c2, j);
                    float cwj = __shfl_sync(FULLMASK, cwv, j);
                    kn0[mm] += c1j*accf[kk][mm][0] + c2j*hbv.x;
                    kn1[mm] += c1j*accf[kk][mm][1] + c2j*hbv.y;
                    kdn[mm] += cwj;
                }
            }
        }
        __syncwarp();

        // ---- stage C: Klein midpoint normalize -> agg (transposed into XT) ----
        float axagg[4];
        #pragma unroll
        for (int mm=0;mm<4;mm++){
            float ikd = __fdividef(1.0f, fmaxf(kdn[mm], MINV));
            float k0 = kn0[mm]*ikd, k1 = kn1[mm]*ikd;
            float kk2 = wred(k0*k0 + k1*k1);
            float s2 = __fdividef(1.0f, 1.0f + sqrtf(fmaxf(1.0f - kk2, MINV)));
            float p0 = s2*k0, p1 = s2*k1;
            float p2 = s2*s2*kk2;
            float spp = 1.0f;
            { float pn = sqrtf(fmaxf(p2, MINV));
              if (pn > MAXN){ spp = __fdividef(MAXN, pn); p2 = MAXN*MAXN; } }
            p0 *= spp; p1 *= spp;
            { float nn = sqrtf(fmaxf(p2, MINV)); axagg[mm] = __fdividef(artanh_c(nn), nn); }
            XT[(2*l+0)*4 + mm] = p0;
            XT[(2*l+1)*4 + mm] = p1;
        }
        __syncwarp();

        // ---- stage D1: packed matvec ----
        u64t h1p[4][2];
        #pragma unroll
        for (int c=0;c<4;c++){ h1p[c][0]=0ull; h1p[c][1]=0ull; }
        #pragma unroll 2
        for (int j2=0;j2<32;j2++){
            ulonglong2 xe = *(const ulonglong2*)(XT + (2*j2+0)*4);
            ulonglong2 xo = *(const ulonglong2*)(XT + (2*j2+1)*4);
            uint4 w = *(const uint4*)(HF1 + j2*256 + 8*l);
            {   float2 f0 = __half22float2(*(const __half2*)&w.x);
                float2 f1 = __half22float2(*(const __half2*)&w.y);
                u64t wc0=dup2(f0.x), wc1=dup2(f0.y), wc2=dup2(f1.x), wc3=dup2(f1.y);
                fma2(h1p[0][0], wc0, xe.x); fma2(h1p[0][1], wc0, xe.y);
                fma2(h1p[1][0], wc1, xe.x); fma2(h1p[1][1], wc1, xe.y);
                fma2(h1p[2][0], wc2, xe.x); fma2(h1p[2][1], wc2, xe.y);
                fma2(h1p[3][0], wc3, xe.x); fma2(h1p[3][1], wc3, xe.y); }
            {   float2 f0 = __half22float2(*(const __half2*)&w.z);
                float2 f1 = __half22float2(*(const __half2*)&w.w);
                u64t wc0=dup2(f0.x), wc1=dup2(f0.y), wc2=dup2(f1.x), wc3=dup2(f1.y);
                fma2(h1p[0][0], wc0, xo.x); fma2(h1p[0][1], wc0, xo.y);
                fma2(h1p[1][0], wc1, xo.x); fma2(h1p[1][1], wc1, xo.y);
                fma2(h1p[2][0], wc2, xo.x); fma2(h1p[2][1], wc2, xo.y);
                fma2(h1p[3][0], wc3, xo.x); fma2(h1p[3][1], wc3, xo.y); }
        }
        float h1[4][4];
        #pragma unroll
        for (int c=0;c<4;c++)
            #pragma unroll
            for (int pr=0;pr<2;pr++){
                float2 t = unp(h1p[c][pr]);
                h1[2*pr+0][c] = t.x;
                h1[2*pr+1][c] = t.y;
            }
        __syncwarp();
        float ax1[4];
        {
            float bv1[4] = {FB1H[4*l], FB1H[4*l+1], FB1H[4*l+2], FB1H[4*l+3]};
            const float fb1h2 = SC[8];
            #pragma unroll
            for (int mm=0;mm<4;mm++){
                float n2o;
                blin_nl<4>(h1[mm], bv1, fb1h2, axagg[mm], true, ax1[mm], n2o);
            }
        }
        #pragma unroll
        for (int c=0;c<4;c++)
            *(float4*)(ST2 + (4*l+c)*4) = make_float4(h1[0][c], h1[1][c], h1[2][c], h1[3][c]);
        __syncwarp();

        // ---- stage D2: packed matvec + Klein accumulation ----
        u64t h2p[4][2];
        #pragma unroll
        for (int c=0;c<4;c++){ h2p[c][0]=0ull; h2p[c][1]=0ull; }
        #pragma unroll 2
        for (int j2=0;j2<64;j2++){
            ulonglong2 xe = *(const ulonglong2*)(ST2 + (2*j2+0)*4);
            ulonglong2 xo = *(const ulonglong2*)(ST2 + (2*j2+1)*4);
            uint4 w = *(const uint4*)(HF2 + j2*256 + 8*l);
            {   float2 f0 = __half22float2(*(const __half2*)&w.x);
                float2 f1 = __half22float2(*(const __half2*)&w.y);
                u64t wc0=dup2(f0.x), wc1=dup2(f0.y), wc2=dup2(f1.x), wc3=dup2(f1.y);
                fma2(h2p[0][0], wc0, xe.x); fma2(h2p[0][1], wc0, xe.y);
                fma2(h2p[1][0], wc1, xe.x); fma2(h2p[1][1], wc1, xe.y);
                fma2(h2p[2][0], wc2, xe.x); fma2(h2p[2][1], wc2, xe.y);
                fma2(h2p[3][0], wc3, xe.x); fma2(h2p[3][1], wc3, xe.y); }
            {   float2 f0 = __half22float2(*(const __half2*)&w.z);
                float2 f1 = __half22float2(*(const __half2*)&w.w);
                u64t wc0=dup2(f0.x), wc1=dup2(f0.y), wc2=dup2(f1.x), wc3=dup2(f1.y);
                fma2(h2p[0][0], wc0, xo.x); fma2(h2p[0][1], wc0, xo.y);
                fma2(h2p[1][0], wc1, xo.x); fma2(h2p[1][1], wc1, xo.y);
                fma2(h2p[2][0], wc2, xo.x); fma2(h2p[2][1], wc2, xo.y);
                fma2(h2p[3][0], wc3, xo.x); fma2(h2p[3][1], wc3, xo.y); }
        }
        float h2a[4][4];
        #pragma unroll
        for (int c=0;c<4;c++)
            #pragma unroll
            for (int pr=0;pr<2;pr++){
                float2 t = unp(h2p[c][pr]);
                h2a[2*pr+0][c] = t.x;
                h2a[2*pr+1][c] = t.y;
            }
        {
            float bv2[4] = {FB2H[4*l], FB2H[4*l+1], FB2H[4*l+2], FB2H[4*l+3]};
            const float fb2h2 = SC[9];
            #pragma unroll
            for (int mm=0;mm<4;mm++){
                float axo, r2o;
                blin_nl<4>(h2a[mm], bv2, fb2h2, ax1[mm], false, axo, r2o);
                float fk  = __fdividef(2.0f, 1.0f + r2o);
                float kk2 = fk*fk*r2o;
                float lor = rsqrtf(fmaxf(1.0f - kk2, MINV));
                float cw  = S[SOFF_MASK + mm]*lor;
                float cf  = cw*fk;
                mden += cw;
                #pragma unroll
                for (int c=0;c<4;c++) mnum[c] += cf*h2a[mm][c];
            }
        }
        __syncwarp();
    }

    // ---- neighbor Klein midpoint -> mid (128-d) ----
    float imd = __fdividef(1.0f, fmaxf(mden, MINV));
    float mk4[4]; float s = 0.f;
    #pragma unroll
    for (int c=0;c<4;c++){ mk4[c] = mnum[c]*imd; s += mk4[c]*mk4[c]; }
    float kk2 = wred(s);
    float s2 = __fdividef(1.0f, 1.0f + sqrtf(fmaxf(1.0f - kk2, MINV)));
    float p2 = s2*s2*kk2;
    float spp = 1.0f;
    { float pn = sqrtf(fmaxf(p2, MINV));
      if (pn > MAXN){ spp = __fdividef(MAXN, pn); p2 = MAXN*MAXN; } }
    float cc = s2*spp;
    #pragma unroll
    for (int c=0;c<4;c++) mk4[c] *= cc;
    *(float4*)(ST2 + 4*l) = make_float4(mk4[0], mk4[1], mk4[2], mk4[3]);
    float axmid;
    { float nn = sqrtf(fmaxf(p2, MINV)); axmid = __fdividef(artanh_c(nn), nn); }
    __syncwarp();

    // ---- tail E1 ----
    float g1v[2] = {0.f, 0.f};
    #pragma unroll 4
    for (int i4=0;i4<32;i4++){
        float4 xs = *(const float4*)(ST2 + i4*4);
        float4 w0 = __ldg((const float4*)(gw1 + (2*l)*128 + i4*4));
        float4 w1 = __ldg((const float4*)(gw1 + (2*l+1)*128 + i4*4));
        g1v[0] += w0.x*xs.x + w0.y*xs.y + w0.z*xs.z + w0.w*xs.w;
        g1v[1] += w1.x*xs.x + w1.y*xs.y + w1.z*xs.z + w1.w*xs.w;
    }
    __syncwarp();
    float axo1, r2o1;
    {
        float bvg1[2] = {GB1H[2*l], GB1H[2*l+1]};
        blin_nl<2>(g1v, bvg1, SC[10], axmid, true, axo1, r2o1);
    }
    *(float2*)(ST2 + 2*l) = make_float2(g1v[0], g1v[1]);
    __syncwarp();

    // ---- tail E2 ----
    float g2v[2] = {0.f, 0.f};
    #pragma unroll 4
    for (int i4=0;i4<16;i4++){
        float4 xs = *(const float4*)(ST2 + i4*4);
        float4 w0 = __ldg((const float4*)(gw2 + (2*l)*64 + i4*4));
        float4 w1 = __ldg((const float4*)(gw2 + (2*l+1)*64 + i4*4));
        g2v[0] += w0.x*xs.x + w0.y*xs.y + w0.z*xs.z + w0.w*xs.w;
        g2v[1] += w1.x*xs.x + w1.y*xs.y + w1.z*xs.z + w1.w*xs.w;
    }
    float axo2, r2o2;
    {
        float bvg2[2] = {GB2H[2*l], GB2H[2*l+1]};
        blin_nl<2>(g2v, bvg2, SC[11], axo1, false, axo2, r2o2);
    }
    *(float2*)(out + node*64 + 2*l) = make_float2(g2v[0], g2v[1]);
}

extern "C" void kernel_launch(void* const* d_in, const int* in_sizes, int n_in,
                              void* d_out, int out_size){
    const float* x       = (const float*)d_in[0];
    const int*   nei     = (const int*)  d_in[1];
    const float* neimask = (const float*)d_in[2];
    const float* kt      = (const float*)d_in[3];
    const float* lin_w   = (const float*)d_in[4];
    const float* lin_b   = (const float*)d_in[5];
    const float* fw1     = (const float*)d_in[6];
    const float* fb1     = (const float*)d_in[7];
    const float* fw2     = (const float*)d_in[8];
    const float* fb2     = (const float*)d_in[9];
    const float* gw1     = (const float*)d_in[10];
    const float* gb1     = (const float*)d_in[11];
    const float* gw2     = (const float*)d_in[12];
    const float* gb2     = (const float*)d_in[13];
    float* out = (float*)d_out;
    const int N = in_sizes[0]/64;

    cudaFuncSetAttribute(kp_main, cudaFuncAttributeMaxDynamicSharedMemorySize, SMEM_BYTES);
    prep_kernel<<<1, 256>>>(kt, lin_b, fb1, fb2, gb1, gb2);
    kp_main<<<(N + NWARP - 1)/NWARP, NTHR, SMEM_BYTES>>>(x, nei, neimask, lin_w, fw1, fw2, gw1, gw2, out, N);
}

// round 16
// speedup vs baseline: 1.2023x; 1.0753x over previous
#include <cuda_runtime.h>
#include <cuda_fp16.h>
#include <cstdint>

#define FULLMASK 0xffffffffu
#define MINV 1e-12f
#define EPSV 1e-6f
#define MAXN (1.0f - 1e-5f)
#define KPI  (1.0f/0.66f)

#define NWARP 28
#define NTHR  (NWARP*32)

// shared layout (float offsets)
#define OFF_W4H   0
#define OFF_FW1H  8192
#define OFF_FW2H  12288
#define OFF_CONST 20480
#define OFF_STAGE 21392
#define WSTRIDE   1056
#define SOFF_ST2  0
#define SOFF_XT   512
#define SOFF_WKM  768
#define SOFF_AARR 784
#define SOFF_MASK 788
#define SOFF_XK   792
#define SOFF_PB   800
#define SMEM_FLOATS (OFF_STAGE + NWARP*WSTRIDE)
#define SMEM_BYTES  (SMEM_FLOATS*4)

typedef unsigned long long u64t;

__device__ float g_const[1024];
// 0 klp[4][64], 256 hb[4][64], 512 fb1h[128], 640 fb2h[128], 768 gb1h[64], 832 gb2h[64], 896 scal[12]

__device__ __forceinline__ float wred(float v){
    v += __shfl_xor_sync(FULLMASK, v, 16);
    v += __shfl_xor_sync(FULLMASK, v, 8);
    v += __shfl_xor_sync(FULLMASK, v, 4);
    v += __shfl_xor_sync(FULLMASK, v, 2);
    v += __shfl_xor_sync(FULLMASK, v, 1);
    return v;
}
__device__ __forceinline__ float tanh_pos(float xx){
    float e = __expf(-2.0f*xx);
    return __fdividef(1.0f - e, 1.0f + e);
}
__device__ __forceinline__ float artanh_c(float xx){
    xx = fminf(fmaxf(xx, -1.0f + EPSV), 1.0f - EPSV);
    return 0.5f*__logf(__fdividef(1.0f + xx, 1.0f - xx));
}
__device__ __forceinline__ u64t dup2(float x){
    u64t r; asm("mov.b64 %0, {%1, %1};" : "=l"(r) : "f"(x)); return r;
}
__device__ __forceinline__ void fma2(u64t& d, u64t a, u64t b){
    asm("fma.rn.f32x2 %0, %1, %2, %0;" : "+l"(d) : "l"(a), "l"(b));
}
__device__ __forceinline__ float2 unp(u64t v){
    float2 r; asm("mov.b64 {%0, %1}, %2;" : "=f"(r.x), "=f"(r.y) : "l"(v)); return r;
}
__device__ __forceinline__ void cpa8(uint32_t saddr, const void* g){
    asm volatile("cp.async.ca.shared.global [%0], [%1], 8;" :: "r"(saddr), "l"(g));
}
#define CP_COMMIT() asm volatile("cp.async.commit_group;")
#define CP_WAIT0()  asm volatile("cp.async.wait_group 0;")

template<int V>
__device__ __forceinline__ void emap(const float* __restrict__ b, float* __restrict__ dst,
                                     float* __restrict__ n2dst, bool doproj){
    int l = threadIdx.x & 31;
    float u[V]; float s = 0.f;
    #pragma unroll
    for (int c=0;c<V;c++){ u[c] = b[V*l+c]; s += u[c]*u[c]; }
    float n2 = wred(s);
    float n  = sqrtf(fmaxf(n2, MINV));
    float f  = __fdividef(tanh_pos(n), n);
    float h2 = f*f*n2;
    if (doproj){
        float pn = sqrtf(fmaxf(h2, MINV));
        if (pn > MAXN){ f *= __fdividef(MAXN, pn); h2 = MAXN*MAXN; }
    }
    #pragma unroll
    for (int c=0;c<V;c++) dst[V*l+c] = f*u[c];
    if (l == 0) *n2dst = h2;
}

__global__ void prep_kernel(const float* __restrict__ kt, const float* __restrict__ lin_b,
                            const float* __restrict__ fb1, const float* __restrict__ fb2,
                            const float* __restrict__ gb1, const float* __restrict__ gb2){
    int w = threadIdx.x >> 5;
    if (w < 4){
        emap<2>(kt + w*64,    g_const + w*64,       g_const + 896 + w, false);
        emap<2>(lin_b + w*64, g_const + 256 + w*64, g_const + 900 + w, true);
    } else if (w == 4) emap<4>(fb1, g_const + 512, g_const + 904, true);
    else if (w == 5)   emap<4>(fb2, g_const + 640, g_const + 905, true);
    else if (w == 6)   emap<2>(gb1, g_const + 768, g_const + 906, true);
    else if (w == 7)   emap<2>(gb2, g_const + 832, g_const + 907, true);
}

// (kept for tail E1/E2 only)
template<int V>
__device__ __forceinline__ void blin_nl(float* h, const float* bvec, float b2,
                                        float ax_in, bool do_act,
                                        float& out_ax, float& out_n2){
    float s = 0.f;
    #pragma unroll
    for (int c=0;c<V;c++) s += h[c]*h[c];
    float mv2 = wred(s);
    float mvn = sqrtf(fmaxf(mv2, MINV));
    float fac = __fdividef(tanh_pos(mvn*ax_in), mvn);
    float f2  = fac*fac*mv2;
    { float pn = sqrtf(fmaxf(f2, MINV));
      if (pn > MAXN){ fac *= __fdividef(MAXN, pn); f2 = MAXN*MAXN; } }
    float mh = 0.f;
    #pragma unroll
    for (int c=0;c<V;c++) mh += h[c]*bvec[c];
    mh = wred(mh);
    float xy  = fac*mh;
    float A   = 1.0f + 2.0f*xy + b2;
    float B   = 1.0f - f2;
    float D   = fmaxf(1.0f + 2.0f*xy + f2*b2, MINV);
    float idn = __fdividef(1.0f, D);
    float r2  = (A*A*f2 + 2.0f*A*B*xy + B*B*b2)*idn*idn;
    float sp  = 1.0f;
    { float rn = sqrtf(fmaxf(r2, MINV));
      if (rn > MAXN){ sp = __fdividef(MAXN, rn); r2 = MAXN*MAXN; } }
    float cA = sp*idn*A*fac, cB = sp*idn*B;
    #pragma unroll
    for (int c=0;c<V;c++) h[c] = cA*h[c] + cB*bvec[c];
    if (do_act){
        float rn = sqrtf(fmaxf(r2, MINV));
        float lm = __fdividef(artanh_c(rn), rn);
        float t = 0.f;
        #pragma unroll
        for (int c=0;c<V;c++){ float u = fmaxf(h[c],0.f)*lm; h[c]=u; t += u*u; }
        float t2 = wred(t);
        float tn = sqrtf(fmaxf(t2, MINV));
        float ef = __fdividef(tanh_pos(tn), tn);
        float o2 = ef*ef*t2;
        float so = 1.0f;
        { float on = sqrtf(fmaxf(o2, MINV));
          if (on > MAXN){ so = __fdividef(MAXN, on); o2 = MAXN*MAXN; } }
        float cc = ef*so;
        #pragma unroll
        for (int c=0;c<V;c++) h[c] *= cc;
        r2 = o2;
    }
    out_n2 = r2;
    float nn = sqrtf(fmaxf(r2, MINV));
    out_ax = __fdividef(artanh_c(nn), nn);
}

__global__ void __launch_bounds__(NTHR, 1)
kp_main(const float* __restrict__ x, const int* __restrict__ nei,
        const float* __restrict__ neimask, const float* __restrict__ lin_w,
        const float* __restrict__ fw1, const float* __restrict__ fw2,
        const float* __restrict__ gw1, const float* __restrict__ gw2,
        float* __restrict__ out, int N)
{
    extern __shared__ float sm[];
    const int tid = threadIdx.x, wid = tid >> 5, l = tid & 31;

    __half* HW  = (__half*)(sm + OFF_W4H);
    __half* HF1 = (__half*)(sm + OFF_FW1H);
    __half* HF2 = (__half*)(sm + OFF_FW2H);

    for (int i = tid; i < 16384; i += NTHR){
        int p = i >> 13, rem = i & 8191, j2 = rem >> 8, q = rem & 255;
        int lane = q >> 3, c8 = q & 7, r01 = c8 >> 2, kk = (c8 >> 1) & 1, oo = c8 & 1;
        int row = 2*j2 + r01, k = 2*p + kk, o = 2*lane + oo;
        HW[i] = __float2half_rn(lin_w[k*4096 + o*64 + row]);
    }
    for (int i = tid; i < 8192; i += NTHR){
        int j2 = i >> 8, q = i & 255, lane = q >> 3, c8 = q & 7, r01 = c8 >> 2, c = c8 & 3;
        int row = 2*j2 + r01, o = 4*lane + c;
        HF1[i] = __float2half_rn(fw1[o*64 + row]);
    }
    for (int i = tid; i < 16384; i += NTHR){
        int j2 = i >> 8, q = i & 255, lane = q >> 3, c8 = q & 7, r01 = c8 >> 2, c = c8 & 3;
        int row = 2*j2 + r01, o = 4*lane + c;
        HF2[i] = __float2half_rn(fw2[o*128 + row]);
    }
    for (int i = tid; i < 908; i += NTHR) sm[OFF_CONST + i] = g_const[i];
    __syncthreads();

    const int node = blockIdx.x*NWARP + wid;
    if (node >= N) return;

    float* S   = sm + OFF_STAGE + wid*WSTRIDE;
    float* ST2 = S + SOFF_ST2;
    float* XT  = S + SOFF_XT;
    float* PB  = S + SOFF_PB;
    const float* KLP  = sm + OFF_CONST;
    const float* HB   = KLP + 256;
    const float* FB1H = KLP + 512;
    const float* FB2H = KLP + 640;
    const float* GB1H = KLP + 768;
    const float* GB2H = KLP + 832;
    const float* SC   = KLP + 896;

    // group-0 neighbor prefetch
    {
        #pragma unroll
        for (int mm=0;mm<4;mm++){
            int idx = __ldg(nei + node*16 + mm);
            uint32_t dst = (uint32_t)__cvta_generic_to_shared(PB + mm*64 + 2*l);
            cpa8(dst, x + (size_t)idx*64 + 2*l);
        }
        CP_COMMIT();
    }

    // center point
    float2 xv = *(const float2*)(x + node*64 + 2*l);
    float x2 = wred(xv.x*xv.x + xv.y*xv.y);
    { float n = sqrtf(fmaxf(x2, MINV));
      if (n > MAXN){ float s = __fdividef(MAXN, n); xv.x*=s; xv.y*=s; x2 = MAXN*MAXN; } }

    {
        float xk[4];
        #pragma unroll
        for (int k=0;k<4;k++){
            float2 kp = *(const float2*)(KLP + k*64 + 2*l);
            xk[k] = wred(xv.x*kp.x + xv.y*kp.y);
        }
        if (l == 0) *(float4*)(S + SOFF_XK) = make_float4(xk[0], xk[1], xk[2], xk[3]);
    }
    __syncwarp();

    float mnum[4] = {0.f,0.f,0.f,0.f};
    float mden = 0.f;

    for (int g = 0; g < 4; g++){
        CP_WAIT0();
        __syncwarp();

        // ---- stage A ----
        float d_n2 = 0.f, d_xdn = 0.f, d_nk = 0.f;
        #pragma unroll
        for (int mm=0; mm<4; mm++){
            float2 v = *(const float2*)(PB + mm*64 + 2*l);
            float n2 = wred(v.x*v.x + v.y*v.y);
            float nn = sqrtf(fmaxf(n2, MINV));
            if (nn > MAXN){ float s = __fdividef(MAXN, nn); v.x*=s; v.y*=s; n2 = MAXN*MAXN; }
            XT[(2*l+0)*4 + mm] = v.x;
            XT[(2*l+1)*4 + mm] = v.y;
            float xdn = wred(xv.x*v.x + xv.y*v.y);
            const bool quad = ((l>>2) == mm);
            if (quad){ d_n2 = n2; d_xdn = xdn; }
            #pragma unroll
            for (int k=0;k<4;k++){
                float2 kp = *(const float2*)(KLP + k*64 + 2*l);
                float nk = wred(v.x*kp.x + v.y*kp.y);
                if (quad && (l&3)==k) d_nk = nk;
            }
        }
        __syncwarp();
        if (g < 3){
            #pragma unroll
            for (int mm=0;mm<4;mm++){
                int idx = __ldg(nei + node*16 + (g+1)*4 + mm);
                uint32_t dst = (uint32_t)__cvta_generic_to_shared(PB + mm*64 + 2*l);
                cpa8(dst, x + (size_t)idx*64 + 2*l);
            }
            CP_COMMIT();
        }
        {   // lane-parallel chain: lane j = mm*4+k
            const int mmj = (l >> 2) & 3, kj = l & 3;
            float xkj   = S[SOFF_XK + kj];
            float klp2j = SC[kj];
            float a   = 1.0f - 2.0f*d_xdn + d_n2;
            float b   = 1.0f - x2;
            float den = fmaxf(1.0f - 2.0f*d_xdn + x2*d_n2, MINV);
            float idn = __fdividef(1.0f, den);
            float x02 = (a*a*x2 - 2.0f*a*b*d_xdn + b*b*d_n2)*idn*idn;
            float s0  = 1.0f;
            { float n0 = sqrtf(fmaxf(x02, MINV));
              if (n0 > MAXN){ s0 = __fdividef(MAXN, n0); x02 = MAXN*MAXN; } }
            float x0k = (-a*xkj + b*d_nk)*idn*s0;
            float A = 1.0f - 2.0f*x0k + klp2j;
            float B = 1.0f - x02;
            float D = fmaxf(1.0f - 2.0f*x0k + x02*klp2j, MINV);
            float iD = __fdividef(1.0f, D);
            float nsq = (A*A*x02 - 2.0f*A*B*x0k + B*B*klp2j)*iD*iD;
            float nd = sqrtf(fmaxf(nsq, MINV));
            float dd = 2.0f*artanh_c(nd);
            float wv = fmaxf(0.f, 1.0f - dd*KPI);
            float sw = wv + __shfl_xor_sync(FULLMASK, wv, 1);
            sw += __shfl_xor_sync(FULLMASK, sw, 2);
            float isw = __fdividef(1.0f, fmaxf(sw, MINV));
            if (l < 16){
                S[SOFF_WKM + l] = wv*isw;
                if (kj == 0){
                    float nn2 = sqrtf(fmaxf(d_n2, MINV));
                    S[SOFF_AARR + mmj] = __fdividef(artanh_c(nn2), nn2);
                    S[SOFF_MASK + mmj] = __ldg(neimask + node*16 + g*4 + mmj);
                }
            }
        }
        __syncwarp();

        // ---- stage B: two k-pair passes, packed f32x2 matvec ----
        float kn0[4], kn1[4], kdn[4];
        #pragma unroll
        for (int mm=0;mm<4;mm++){ kn0[mm]=0.f; kn1[mm]=0.f; kdn[mm]=0.f; }
        #pragma unroll 1
        for (int p=0;p<2;p++){
            u64t acc2[2][2][2];
            #pragma unroll
            for (int kk=0;kk<2;kk++)
                #pragma unroll
                for (int oo=0;oo<2;oo++)
                    #pragma unroll
                    for (int pr=0;pr<2;pr++) acc2[kk][oo][pr] = 0ull;
            #pragma unroll 2
            for (int j2=0;j2<32;j2++){
                ulonglong2 xe = *(const ulonglong2*)(XT + (2*j2+0)*4);
                ulonglong2 xo = *(const ulonglong2*)(XT + (2*j2+1)*4);
                uint4 w = *(const uint4*)(HW + p*8192 + j2*256 + 8*l);
                {   float2 f0 = __half22float2(*(const __half2*)&w.x);
                    float2 f1 = __half22float2(*(const __half2*)&w.y);
                    u64t w00=dup2(f0.x), w01=dup2(f0.y), w10=dup2(f1.x), w11=dup2(f1.y);
                    fma2(acc2[0][0][0], w00, xe.x); fma2(acc2[0][0][1], w00, xe.y);
                    fma2(acc2[0][1][0], w01, xe.x); fma2(acc2[0][1][1], w01, xe.y);
                    fma2(acc2[1][0][0], w10, xe.x); fma2(acc2[1][0][1], w10, xe.y);
                    fma2(acc2[1][1][0], w11, xe.x); fma2(acc2[1][1][1], w11, xe.y); }
                {   float2 f0 = __half22float2(*(const __half2*)&w.z);
                    float2 f1 = __half22float2(*(const __half2*)&w.w);
                    u64t w00=dup2(f0.x), w01=dup2(f0.y), w10=dup2(f1.x), w11=dup2(f1.y);
                    fma2(acc2[0][0][0], w00, xo.x); fma2(acc2[0][0][1], w00, xo.y);
                    fma2(acc2[0][1][0], w01, xo.x); fma2(acc2[0][1][1], w01, xo.y);
                    fma2(acc2[1][0][0], w10, xo.x); fma2(acc2[1][0][1], w10, xo.y);
                    fma2(acc2[1][1][0], w11, xo.x); fma2(acc2[1][1][1], w11, xo.y); }
            }
            float accf[2][4][2];
            #pragma unroll
            for (int kk=0;kk<2;kk++)
                #pragma unroll
                for (int oo=0;oo<2;oo++)
                    #pragma unroll
                    for (int pr=0;pr<2;pr++){
                        float2 t = unp(acc2[kk][oo][pr]);
                        accf[kk][2*pr+0][oo] = t.x;
                        accf[kk][2*pr+1][oo] = t.y;
                    }
            float2 hbv0 = *(const float2*)(HB + (2*p+0)*64 + 2*l);
            float2 hbv1 = *(const float2*)(HB + (2*p+1)*64 + 2*l);
            float d_mx2 = 0.f, d_mh = 0.f;
            #pragma unroll
            for (int kk=0;kk<2;kk++){
                float2 hbv = kk ? hbv1 : hbv0;
                #pragma unroll
                for (int mm=0;mm<4;mm++){
                    float a0=accf[kk][mm][0], a1=accf[kk][mm][1];
                    float mx2 = wred(a0*a0 + a1*a1);
                    float mh  = wred(a0*hbv.x + a1*hbv.y);
                    if (l == kk*4+mm){ d_mx2 = mx2; d_mh = mh; }
                }
            }
            float c1, c2, cwv;
            {
                const int kkj = (l >> 2) & 1, mmj = l & 3;
                const int kj = 2*p + kkj;
                float aa   = S[SOFF_AARR + mmj];
                float hb2k = SC[4 + kj];
                float wkmv = S[SOFF_WKM + mmj*4 + kj];
                float mxn = sqrtf(fmaxf(d_mx2, MINV));
                float fac = __fdividef(tanh_pos(mxn*aa), mxn);
                float f2  = fac*fac*d_mx2;
                { float pn = sqrtf(fmaxf(f2, MINV));
                  if (pn > MAXN){ fac *= __fdividef(MAXN, pn); f2 = MAXN*MAXN; } }
                float xy = fac*d_mh;
                float A = 1.0f + 2.0f*xy + hb2k;
                float B = 1.0f - f2;
                float D = fmaxf(1.0f + 2.0f*xy + f2*hb2k, MINV);
                float iD = __fdividef(1.0f, D);
                float r2 = (A*A*f2 + 2.0f*A*B*xy + B*B*hb2k)*iD*iD;
                float sp = 1.0f;
                { float rn = sqrtf(fmaxf(r2, MINV));
                  if (rn > MAXN){ sp = __fdividef(MAXN, rn); r2 = MAXN*MAXN; } }
                float fk  = __fdividef(2.0f, 1.0f + r2);
                float kk2 = fk*fk*r2;
                float lor = rsqrtf(fmaxf(1.0f - kk2, MINV));
                cwv = wkmv*lor;
                float cf  = cwv*fk*sp*iD;
                c1 = cf*A*fac;
                c2 = cf*B;
            }
            #pragma unroll
            for (int kk=0;kk<2;kk++){
                float2 hbv = kk ? hbv1 : hbv0;
                #pragma unroll
                for (int mm=0;mm<4;mm++){
                    const int j = kk*4+mm;
                    float c1j = __shfl_sync(FULLMASK, c1, j);
                    float c2j = __shfl_sync(FULLMASK, c2, j);
                    float cwj = __shfl_sync(FULLMASK, cwv, j);
                    kn0[mm] += c1j*accf[kk][mm][0] + c2j*hbv.x;
                    kn1[mm] += c1j*accf[kk][mm][1] + c2j*hbv.y;
                    kdn[mm] += cwj;
                }
            }
        }
        __syncwarp();

        // ---- stage C: lane-parallel Klein normalize (chain on lanes 0-3) ----
        float d_q2 = 0.f, d_kdn = 0.f;
        #pragma unroll
        for (int mm=0;mm<4;mm++){
            float q2 = wred(kn0[mm]*kn0[mm] + kn1[mm]*kn1[mm]);
            if (l == mm){ d_q2 = q2; d_kdn = kdn[mm]; }
        }
        float d_axC, cscv;
        {
            float ikd = __fdividef(1.0f, fmaxf(d_kdn, MINV));
            float kk2 = ikd*ikd*d_q2;
            float s2 = __fdividef(1.0f, 1.0f + sqrtf(fmaxf(1.0f - kk2, MINV)));
            float p2 = s2*s2*kk2;
            float spp = 1.0f;
            { float pn = sqrtf(fmaxf(p2, MINV));
              if (pn > MAXN){ spp = __fdividef(MAXN, pn); p2 = MAXN*MAXN; } }
            cscv = s2*spp*ikd;
            float nn = sqrtf(fmaxf(p2, MINV));
            d_axC = __fdividef(artanh_c(nn), nn);
        }
        #pragma unroll
        for (int mm=0;mm<4;mm++){
            float cj = __shfl_sync(FULLMASK, cscv, mm);
            XT[(2*l+0)*4 + mm] = cj*kn0[mm];
            XT[(2*l+1)*4 + mm] = cj*kn1[mm];
        }
        __syncwarp();

        // ---- stage D1: packed matvec ----
        u64t h1p[4][2];
        #pragma unroll
        for (int c=0;c<4;c++){ h1p[c][0]=0ull; h1p[c][1]=0ull; }
        #pragma unroll 2
        for (int j2=0;j2<32;j2++){
            ulonglong2 xe = *(const ulonglong2*)(XT + (2*j2+0)*4);
            ulonglong2 xo = *(const ulonglong2*)(XT + (2*j2+1)*4);
            uint4 w = *(const uint4*)(HF1 + j2*256 + 8*l);
            {   float2 f0 = __half22float2(*(const __half2*)&w.x);
                float2 f1 = __half22float2(*(const __half2*)&w.y);
                u64t wc0=dup2(f0.x), wc1=dup2(f0.y), wc2=dup2(f1.x), wc3=dup2(f1.y);
                fma2(h1p[0][0], wc0, xe.x); fma2(h1p[0][1], wc0, xe.y);
                fma2(h1p[1][0], wc1, xe.x); fma2(h1p[1][1], wc1, xe.y);
                fma2(h1p[2][0], wc2, xe.x); fma2(h1p[2][1], wc2, xe.y);
                fma2(h1p[3][0], wc3, xe.x); fma2(h1p[3][1], wc3, xe.y); }
            {   float2 f0 = __half22float2(*(const __half2*)&w.z);
                float2 f1 = __half22float2(*(const __half2*)&w.w);
                u64t wc0=dup2(f0.x), wc1=dup2(f0.y), wc2=dup2(f1.x), wc3=dup2(f1.y);
                fma2(h1p[0][0], wc0, xo.x); fma2(h1p[0][1], wc0, xo.y);
                fma2(h1p[1][0], wc1, xo.x); fma2(h1p[1][1], wc1, xo.y);
                fma2(h1p[2][0], wc2, xo.x); fma2(h1p[2][1], wc2, xo.y);
                fma2(h1p[3][0], wc3, xo.x); fma2(h1p[3][1], wc3, xo.y); }
        }
        float h1[4][4];
        #pragma unroll
        for (int c=0;c<4;c++)
            #pragma unroll
            for (int pr=0;pr<2;pr++){
                float2 t = unp(h1p[c][pr]);
                h1[2*pr+0][c] = t.x;
                h1[2*pr+1][c] = t.y;
            }
        __syncwarp();

        // ---- D1 epilogue: lane-parallel blinear(act) ----
        float bv1[4] = {FB1H[4*l], FB1H[4*l+1], FB1H[4*l+2], FB1H[4*l+3]};
        float d_mv2 = 0.f, d_mh1 = 0.f;
        #pragma unroll
        for (int mm=0;mm<4;mm++){
            float s=0.f, mh=0.f;
            #pragma unroll
            for (int c=0;c<4;c++){ s += h1[mm][c]*h1[mm][c]; mh += h1[mm][c]*bv1[c]; }
            s = wred(s); mh = wred(mh);
            if (l == mm){ d_mv2 = s; d_mh1 = mh; }
        }
        float cA1, cB1, lm1;
        {
            const float b2 = SC[8];
            float mvn = sqrtf(fmaxf(d_mv2, MINV));
            float fac = __fdividef(tanh_pos(mvn*d_axC), mvn);
            float f2 = fac*fac*d_mv2;
            { float pn = sqrtf(fmaxf(f2, MINV));
              if (pn > MAXN){ fac *= __fdividef(MAXN, pn); f2 = MAXN*MAXN; } }
            float xy = fac*d_mh1;
            float A = 1.0f + 2.0f*xy + b2;
            float B = 1.0f - f2;
            float D = fmaxf(1.0f + 2.0f*xy + f2*b2, MINV);
            float iD = __fdividef(1.0f, D);
            float r2 = (A*A*f2 + 2.0f*A*B*xy + B*B*b2)*iD*iD;
            float sp = 1.0f;
            { float rn = sqrtf(fmaxf(r2, MINV));
              if (rn > MAXN){ sp = __fdividef(MAXN, rn); r2 = MAXN*MAXN; } }
            cA1 = sp*iD*A*fac; cB1 = sp*iD*B;
            float rn = sqrtf(fmaxf(r2, MINV));
            lm1 = __fdividef(artanh_c(rn), rn);
        }
        float d_t2 = 0.f;
        #pragma unroll
        for (int mm=0;mm<4;mm++){
            float cAj = __shfl_sync(FULLMASK, cA1, mm);
            float cBj = __shfl_sync(FULLMASK, cB1, mm);
            float lmj = __shfl_sync(FULLMASK, lm1, mm);
            float t = 0.f;
            #pragma unroll
            for (int c=0;c<4;c++){
                float u = fmaxf(cAj*h1[mm][c] + cBj*bv1[c], 0.f)*lmj;
                h1[mm][c] = u; t += u*u;
            }
            t = wred(t);
            if (l == mm) d_t2 = t;
        }
        float cc1, d_ax1;
        {
            float tn = sqrtf(fmaxf(d_t2, MINV));
            float ef = __fdividef(tanh_pos(tn), tn);
            float o2 = ef*ef*d_t2;
            float so = 1.0f;
            { float on = sqrtf(fmaxf(o2, MINV));
              if (on > MAXN){ so = __fdividef(MAXN, on); o2 = MAXN*MAXN; } }
            cc1 = ef*so;
            float nn = sqrtf(fmaxf(o2, MINV));
            d_ax1 = __fdividef(artanh_c(nn), nn);
        }
        #pragma unroll
        for (int mm=0;mm<4;mm++){
            float ccj = __shfl_sync(FULLMASK, cc1, mm);
            #pragma unroll
            for (int c=0;c<4;c++) h1[mm][c] *= ccj;
        }
        #pragma unroll
        for (int c=0;c<4;c++)
            *(float4*)(ST2 + (4*l+c)*4) = make_float4(h1[0][c], h1[1][c], h1[2][c], h1[3][c]);
        __syncwarp();

        // ---- stage D2: packed matvec ----
        u64t h2p[4][2];
        #pragma unroll
        for (int c=0;c<4;c++){ h2p[c][0]=0ull; h2p[c][1]=0ull; }
        #pragma unroll 2
        for (int j2=0;j2<64;j2++){
            ulonglong2 xe = *(const ulonglong2*)(ST2 + (2*j2+0)*4);
            ulonglong2 xo = *(const ulonglong2*)(ST2 + (2*j2+1)*4);
            uint4 w = *(const uint4*)(HF2 + j2*256 + 8*l);
            {   float2 f0 = __half22float2(*(const __half2*)&w.x);
                float2 f1 = __half22float2(*(const __half2*)&w.y);
                u64t wc0=dup2(f0.x), wc1=dup2(f0.y), wc2=dup2(f1.x), wc3=dup2(f1.y);
                fma2(h2p[0][0], wc0, xe.x); fma2(h2p[0][1], wc0, xe.y);
                fma2(h2p[1][0], wc1, xe.x); fma2(h2p[1][1], wc1, xe.y);
                fma2(h2p[2][0], wc2, xe.x); fma2(h2p[2][1], wc2, xe.y);
                fma2(h2p[3][0], wc3, xe.x); fma2(h2p[3][1], wc3, xe.y); }
            {   float2 f0 = __half22float2(*(const __half2*)&w.z);
                float2 f1 = __half22float2(*(const __half2*)&w.w);
                u64t wc0=dup2(f0.x), wc1=dup2(f0.y), wc2=dup2(f1.x), wc3=dup2(f1.y);
                fma2(h2p[0][0], wc0, xo.x); fma2(h2p[0][1], wc0, xo.y);
                fma2(h2p[1][0], wc1, xo.x); fma2(h2p[1][1], wc1, xo.y);
                fma2(h2p[2][0], wc2, xo.x); fma2(h2p[2][1], wc2, xo.y);
                fma2(h2p[3][0], wc3, xo.x); fma2(h2p[3][1], wc3, xo.y); }
        }
        float h2a[4][4];
        #pragma unroll
        for (int c=0;c<4;c++)
            #pragma unroll
            for (int pr=0;pr<2;pr++){
                float2 t = unp(h2p[c][pr]);
                h2a[2*pr+0][c] = t.x;
                h2a[2*pr+1][c] = t.y;
            }

        // ---- D2 epilogue: lane-parallel blinear + Klein accumulation ----
        float bv2[4] = {FB2H[4*l], FB2H[4*l+1], FB2H[4*l+2], FB2H[4*l+3]};
        float d2_mv2 = 0.f, d2_mh = 0.f;
        #pragma unroll
        for (int mm=0;mm<4;mm++){
            float s=0.f, mh=0.f;
            #pragma unroll
            for (int c=0;c<4;c++){ s += h2a[mm][c]*h2a[mm][c]; mh += h2a[mm][c]*bv2[c]; }
            s = wred(s); mh = wred(mh);
            if (l == mm){ d2_mv2 = s; d2_mh = mh; }
        }
        float e1v, e2v, cwv2;
        {
            const float b2 = SC[9];
            float mvn = sqrtf(fmaxf(d2_mv2, MINV));
            float fac = __fdividef(tanh_pos(mvn*d_ax1), mvn);
            float f2 = fac*fac*d2_mv2;
            { float pn = sqrtf(fmaxf(f2, MINV));
              if (pn > MAXN){ fac *= __fdividef(MAXN, pn); f2 = MAXN*MAXN; } }
            float xy = fac*d2_mh;
            float A = 1.0f + 2.0f*xy + b2;
            float B = 1.0f - f2;
            float D = fmaxf(1.0f + 2.0f*xy + f2*b2, MINV);
            float iD = __fdividef(1.0f, D);
            float r2 = (A*A*f2 + 2.0f*A*B*xy + B*B*b2)*iD*iD;
            float sp = 1.0f;
            { float rn = sqrtf(fmaxf(r2, MINV));
              if (rn > MAXN){ sp = __fdividef(MAXN, rn); r2 = MAXN*MAXN; } }
            float cA = sp*iD*A*fac, cB = sp*iD*B;
            float fk = __fdividef(2.0f, 1.0f + r2);
            float kk2v = fk*fk*r2;
            float lor = rsqrtf(fmaxf(1.0f - kk2v, MINV));
            float msk = S[SOFF_MASK + (l & 3)];
            cwv2 = msk*lor;
            float cf = cwv2*fk;
            e1v = cf*cA; e2v = cf*cB;
        }
        #pragma unroll
        for (int mm=0;mm<4;mm++){
            float e1j = __shfl_sync(FULLMASK, e1v, mm);
            float e2j = __shfl_sync(FULLMASK, e2v, mm);
            float cwj = __shfl_sync(FULLMASK, cwv2, mm);
            mden += cwj;
            #pragma unroll
            for (int c=0;c<4;c++) mnum[c] += e1j*h2a[mm][c] + e2j*bv2[c];
        }
        __syncwarp();
    }

    // ---- neighbor Klein midpoint -> mid (128-d) ----
    float imd = __fdividef(1.0f, fmaxf(mden, MINV));
    float mk4[4]; float s = 0.f;
    #pragma unroll
    for (int c=0;c<4;c++){ mk4[c] = mnum[c]*imd; s += mk4[c]*mk4[c]; }
    float kk2 = wred(s);
    float s2 = __fdividef(1.0f, 1.0f + sqrtf(fmaxf(1.0f - kk2, MINV)));
    float p2 = s2*s2*kk2;
    float spp = 1.0f;
    { float pn = sqrtf(fmaxf(p2, MINV));
      if (pn > MAXN){ spp = __fdividef(MAXN, pn); p2 = MAXN*MAXN; } }
    float cc = s2*spp;
    #pragma unroll
    for (int c=0;c<4;c++) mk4[c] *= cc;
    *(float4*)(ST2 + 4*l) = make_float4(mk4[0], mk4[1], mk4[2], mk4[3]);
    float axmid;
    { float nn = sqrtf(fmaxf(p2, MINV)); axmid = __fdividef(artanh_c(nn), nn); }
    __syncwarp();

    // ---- tail E1 ----
    float g1v[2] = {0.f, 0.f};
    #pragma unroll 4
    for (int i4=0;i4<32;i4++){
        float4 xs = *(const float4*)(ST2 + i4*4);
        float4 w0 = __ldg((const float4*)(gw1 + (2*l)*128 + i4*4));
        float4 w1 = __ldg((const float4*)(gw1 + (2*l+1)*128 + i4*4));
        g1v[0] += w0.x*xs.x + w0.y*xs.y + w0.z*xs.z + w0.w*xs.w;
        g1v[1] += w1.x*xs.x + w1.y*xs.y + w1.z*xs.z + w1.w*xs.w;
    }
    __syncwarp();
    float axo1, r2o1;
    {
        float bvg1[2] = {GB1H[2*l], GB1H[2*l+1]};
        blin_nl<2>(g1v, bvg1, SC[10], axmid, true, axo1, r2o1);
    }
    *(float2*)(ST2 + 2*l) = make_float2(g1v[0], g1v[1]);
    __syncwarp();

    // ---- tail E2 ----
    float g2v[2] = {0.f, 0.f};
    #pragma unroll 4
    for (int i4=0;i4<16;i4++){
        float4 xs = *(const float4*)(ST2 + i4*4);
        float4 w0 = __ldg((const float4*)(gw2 + (2*l)*64 + i4*4));
        float4 w1 = __ldg((const float4*)(gw2 + (2*l+1)*64 + i4*4));
        g2v[0] += w0.x*xs.x + w0.y*xs.y + w0.z*xs.z + w0.w*xs.w;
        g2v[1] += w1.x*xs.x + w1.y*xs.y + w1.z*xs.z + w1.w*xs.w;
    }
    float axo2, r2o2;
    {
        float bvg2[2] = {GB2H[2*l], GB2H[2*l+1]};
        blin_nl<2>(g2v, bvg2, SC[11], axo1, false, axo2, r2o2);
    }
    *(float2*)(out + node*64 + 2*l) = make_float2(g2v[0], g2v[1]);
}

extern "C" void kernel_launch(void* const* d_in, const int* in_sizes, int n_in,
                              void* d_out, int out_size){
    const float* x       = (const float*)d_in[0];
    const int*   nei     = (const int*)  d_in[1];
    const float* neimask = (const float*)d_in[2];
    const float* kt      = (const float*)d_in[3];
    const float* lin_w   = (const float*)d_in[4];
    const float* lin_b   = (const float*)d_in[5];
    const float* fw1     = (const float*)d_in[6];
    const float* fb1     = (const float*)d_in[7];
    const float* fw2     = (const float*)d_in[8];
    const float* fb2     = (const float*)d_in[9];
    const float* gw1     = (const float*)d_in[10];
    const float* gb1     = (const float*)d_in[11];
    const float* gw2     = (const float*)d_in[12];
    const float* gb2     = (const float*)d_in[13];
    float* out = (float*)d_out;
    const int N = in_sizes[0]/64;

    cudaFuncSetAttribute(kp_main, cudaFuncAttributeMaxDynamicSharedMemorySize, SMEM_BYTES);
    prep_kernel<<<1, 256>>>(kt, lin_b, fb1, fb2, gb1, gb2);
    kp_main<<<(N + NWARP - 1)/NWARP, NTHR, SMEM_BYTES>>>(x, nei, neimask, lin_w, fw1, fw2, gw1, gw2, out, N);
}